// round 13
// baseline (speedup 1.0000x reference)
#include <cuda_runtime.h>
#include <cuda_fp16.h>
#include <cstdint>

#define BT 384
#define NN 325
#define MT (BT*NN)     // 124800
#define RT 3           // row-tiles per GEMM CTA (975 = 3*325)

// ---------------- scratch (device globals; zero-initialized) -----------
__device__ __half g_xn     [(size_t)MT*128];
__device__ __half g_qkvh   [(size_t)MT*384];
__device__ float  g_coords [(size_t)MT*2];
__device__ __half g_u      [(size_t)MT*128];
__device__ __half g_vnT    [(size_t)BT*130*384];  // rows 0 and 129 stay zero
__device__ __half g_attnout[(size_t)MT*128];
__device__ float  g_gateres[(size_t)MT*128];
__device__ __half g_sg     [(size_t)MT*128];
__device__ __half g_wqkv   [384*128];
__device__ __half g_w1     [256*128];
__device__ __half g_wo     [128*128];
__device__ __half g_w2     [128*128];
__device__ __half g_cwt    [3*384*384];           // [tap][n pad384][m pad384]

// ---------------- helpers ----------------
__device__ __forceinline__ unsigned sptr(const void* p) {
    return (unsigned)__cvta_generic_to_shared(p);
}
__device__ __forceinline__ void cp16(unsigned dst, const void* src, bool pred) {
    int sz = pred ? 16 : 0;
    asm volatile("cp.async.ca.shared.global [%0], [%1], 16, %2;\n"
                 :: "r"(dst), "l"(src), "r"(sz));
}
#define CP_COMMIT() asm volatile("cp.async.commit_group;\n")
#define CP_WAIT0()  asm volatile("cp.async.wait_group 0;\n")
#define CP_WAIT1()  asm volatile("cp.async.wait_group 1;\n")

__device__ __forceinline__ void ldsm4(unsigned* r, unsigned addr) {
    asm volatile("ldmatrix.sync.aligned.m8n8.x4.shared.b16 {%0,%1,%2,%3}, [%4];\n"
                 : "=r"(r[0]), "=r"(r[1]), "=r"(r[2]), "=r"(r[3]) : "r"(addr));
}
__device__ __forceinline__ void ldsm4t(unsigned* r, unsigned addr) {
    asm volatile("ldmatrix.sync.aligned.m8n8.x4.trans.shared.b16 {%0,%1,%2,%3}, [%4];\n"
                 : "=r"(r[0]), "=r"(r[1]), "=r"(r[2]), "=r"(r[3]) : "r"(addr));
}
__device__ __forceinline__ void mma_f16(float* c, const unsigned* a, unsigned b0, unsigned b1) {
    asm volatile("mma.sync.aligned.m16n8k16.row.col.f32.f16.f16.f32 "
                 "{%0,%1,%2,%3}, {%4,%5,%6,%7}, {%8,%9}, {%0,%1,%2,%3};\n"
                 : "+f"(c[0]), "+f"(c[1]), "+f"(c[2]), "+f"(c[3])
                 : "r"(a[0]), "r"(a[1]), "r"(a[2]), "r"(a[3]), "r"(b0), "r"(b1));
}
__device__ __forceinline__ unsigned h2u(__half2 h) {
    unsigned u; memcpy(&u, &h, 4); return u;
}

// ---------------- prep: weights -> half, transposed --------------------
__global__ __launch_bounds__(256)
void prep_kernel(const float* __restrict__ Wqkv, const float* __restrict__ W1,
                 const float* __restrict__ Wo, const float* __restrict__ W2,
                 const float* __restrict__ cw,
                 __half* __restrict__ oq, __half* __restrict__ o1,
                 __half* __restrict__ oo, __half* __restrict__ o2,
                 __half* __restrict__ ocw)
{
    int i = blockIdx.x * 256 + threadIdx.x;
    if (i < 49152) { int n = i >> 7, k = i & 127;
        oq[n*128 + k] = __float2half_rn(Wqkv[(size_t)k*384 + n]); return; }
    i -= 49152;
    if (i < 32768) { int n = i >> 7, k = i & 127;
        o1[n*128 + k] = __float2half_rn(W1[(size_t)k*256 + n]); return; }
    i -= 32768;
    if (i < 16384) { int n = i >> 7, k = i & 127;
        oo[n*128 + k] = __float2half_rn(Wo[(size_t)k*128 + n]); return; }
    i -= 16384;
    if (i < 16384) { int n = i >> 7, k = i & 127;
        o2[n*128 + k] = __float2half_rn(W2[(size_t)k*128 + n]); return; }
    i -= 16384;
    if (i < 316875) {   // 3*325*325
        int t = i / 105625, rem = i % 105625;
        int n = rem / 325, m = rem % 325;
        ocw[(size_t)t*384*384 + n*384 + m] =
            __float2half_rn(cw[((size_t)n*325 + m)*3 + t]);
    }
}

// ---------------- LayerNorm(x) -> xn half + coords fp32 ----------------
__global__ __launch_bounds__(256)
void ln_kernel(const float* __restrict__ in, __half* __restrict__ out,
               const float* __restrict__ gam, const float* __restrict__ bet,
               float* __restrict__ coords,
               const float* __restrict__ Wl, const float* __restrict__ bl)
{
    int row = blockIdx.x * 8 + (threadIdx.x >> 5);
    if (row >= MT) return;
    int lane = threadIdx.x & 31;
    float4 v = *(const float4*)(in + (size_t)row * 128 + lane * 4);
    float s  = v.x + v.y + v.z + v.w;
    float ss = v.x*v.x + v.y*v.y + v.z*v.z + v.w*v.w;
#pragma unroll
    for (int o = 16; o > 0; o >>= 1) {
        s  += __shfl_xor_sync(0xffffffffu, s,  o);
        ss += __shfl_xor_sync(0xffffffffu, ss, o);
    }
    float mean = s * (1.f/128.f);
    float var  = ss * (1.f/128.f) - mean * mean;
    float r = rsqrtf(var + 1e-5f);
    int c = lane * 4;
    float o0 = (v.x - mean) * r * gam[c+0] + bet[c+0];
    float o1 = (v.y - mean) * r * gam[c+1] + bet[c+1];
    float o2 = (v.z - mean) * r * gam[c+2] + bet[c+2];
    float o3 = (v.w - mean) * r * gam[c+3] + bet[c+3];
    __half2* orow = (__half2*)(out + (size_t)row * 128);
    orow[lane*2]     = __floats2half2_rn(o0, o1);
    orow[lane*2 + 1] = __floats2half2_rn(o2, o3);
    float c0 = o0*Wl[(c+0)*2] + o1*Wl[(c+1)*2] + o2*Wl[(c+2)*2] + o3*Wl[(c+3)*2];
    float c1 = o0*Wl[(c+0)*2+1] + o1*Wl[(c+1)*2+1] + o2*Wl[(c+2)*2+1] + o3*Wl[(c+3)*2+1];
#pragma unroll
    for (int o = 16; o > 0; o >>= 1) {
        c0 += __shfl_xor_sync(0xffffffffu, c0, o);
        c1 += __shfl_xor_sync(0xffffffffu, c1, o);
    }
    if (lane == 0) {
        coords[(size_t)row*2 + 0] = c0 + bl[0];
        coords[(size_t)row*2 + 1] = c1 + bl[1];
    }
}

// ======== common pieces (tiles: rows of 128 halves = 64 u32, stride 68) =
#define WARP_DECLS \
    const int lane = tid & 31, wid = tid >> 5; \
    const int wm = wid >> 1, wn = wid & 1;     \
    const int qg = lane >> 2, rg = lane & 3;

#define MAINLOOP_128(As, Bs) do {                                            \
    unsigned aaddr[2], baddr[4];                                             \
    _Pragma("unroll")                                                        \
    for (int mt = 0; mt < 2; mt++)                                           \
        aaddr[mt] = sptr((As) + (wm*32 + mt*16 + (lane & 15))*68 + ((lane >> 4) << 2)); \
    _Pragma("unroll")                                                        \
    for (int p = 0; p < 4; p++)                                              \
        baddr[p] = sptr((Bs) + (wn*64 + p*16 + (lane & 7) + ((lane >> 4) << 3))*68 + (((lane >> 3) & 1) << 2)); \
    _Pragma("unroll")                                                        \
    for (int s = 0; s < 8; s++) {                                            \
        unsigned a[2][4], b[4][4];                                           \
        _Pragma("unroll")                                                    \
        for (int mt = 0; mt < 2; mt++) ldsm4(a[mt], aaddr[mt] + s*32);       \
        _Pragma("unroll")                                                    \
        for (int p = 0; p < 4; p++) ldsm4(b[p], baddr[p] + s*32);            \
        _Pragma("unroll")                                                    \
        for (int mt = 0; mt < 2; mt++)                                       \
            _Pragma("unroll")                                                \
            for (int p = 0; p < 4; p++) {                                    \
                mma_f16(acc[mt][2*p],     a[mt], b[p][0], b[p][1]);          \
                mma_f16(acc[mt][2*p + 1], a[mt], b[p][2], b[p][3]);          \
            }                                                                \
    }                                                                        \
} while (0)

#define ACC_DECL float acc[2][8][4];                                         \
    _Pragma("unroll") for (int a_=0;a_<2;a_++)                               \
    _Pragma("unroll") for (int b_=0;b_<8;b_++)                               \
    _Pragma("unroll") for (int c_=0;c_<4;c_++) acc[a_][b_][c_] = 0.f;

// 128-row half tile load: 8 cp16 per thread
#define LA_TILE(dst, src) do {                                               \
    _Pragma("unroll")                                                        \
    for (int i_ = 0; i_ < 8; i_++) {                                         \
        int lin = tid + 256*i_; int r_ = lin >> 4, ch = lin & 15;            \
        cp16(sptr((dst) + r_*68 + ch*4), (src) + (size_t)r_*128 + ch*8, true); \
    }                                                                        \
} while (0)

// ---------------- dense GEMM (K=128), RT row-tiles per CTA --------------
// EPI: 0 = +bias -> half [row][384] ; 1 = +bias -> float[128] ;
//      2 = +bias, relu, +res -> float[128]
template<int EPI>
__global__ __launch_bounds__(256, 2)
void gemm_h(const __half* __restrict__ A, const __half* __restrict__ Bw,
            void* __restrict__ Cout, const float* __restrict__ bias,
            const float* __restrict__ res)
{
    extern __shared__ unsigned sm[];
    unsigned* Bs = sm;             // [128][68]
    unsigned* As = sm + 128*68;    // [2][128][68]
    const int tid = threadIdx.x;
    const int col0 = blockIdx.x * 128;
    const int tbase = blockIdx.y * RT;
    LA_TILE(Bs, Bw + (size_t)col0*128);
    LA_TILE(As, A + (size_t)tbase*128*128);
    CP_COMMIT();
    LA_TILE(As + 128*68, A + (size_t)(tbase + 1)*128*128);
    CP_COMMIT();
    WARP_DECLS
#pragma unroll 1
    for (int t = 0; t < RT; t++) {
        if (t == RT - 1) CP_WAIT0(); else CP_WAIT1();
        __syncthreads();
        ACC_DECL
        MAINLOOP_128(As + (t & 1)*128*68, Bs);
        __syncthreads();
        if (t + 2 < RT) {
            LA_TILE(As + (t & 1)*128*68, A + (size_t)(tbase + t + 2)*128*128);
            CP_COMMIT();
        }
        const int row0 = (tbase + t) * 128;
#pragma unroll
        for (int mt = 0; mt < 2; mt++)
#pragma unroll
            for (int i2 = 0; i2 < 2; i2++) {
                int r = row0 + wm*32 + mt*16 + qg + i2*8;
#pragma unroll
                for (int nt = 0; nt < 8; nt++) {
                    int c = col0 + wn*64 + nt*8 + rg*2;
                    float v0 = acc[mt][nt][i2*2]     + bias[c];
                    float v1 = acc[mt][nt][i2*2 + 1] + bias[c + 1];
                    if (EPI == 0) {
                        *(__half2*)((__half*)Cout + (size_t)r*384 + c) = __floats2half2_rn(v0, v1);
                    } else if (EPI == 1) {
                        float* C = (float*)Cout;
                        C[(size_t)r*128 + c]     = v0;
                        C[(size_t)r*128 + c + 1] = v1;
                    } else {
                        float* C = (float*)Cout;
                        C[(size_t)r*128 + c]     = fmaxf(v0, 0.f) + res[(size_t)r*128 + c];
                        C[(size_t)r*128 + c + 1] = fmaxf(v1, 0.f) + res[(size_t)r*128 + c + 1];
                    }
                }
            }
    }
}

// ---------------- FC1 + fused SGU-LN, RT row-tiles ----------------------
__global__ __launch_bounds__(256, 2)
void fc1_kernel(const __half* __restrict__ A, const __half* __restrict__ Bw,
                __half* __restrict__ u, __half* __restrict__ vnT,
                const float* __restrict__ coords,
                const float* __restrict__ b1,
                const float* __restrict__ aW, const float* __restrict__ ab,
                const float* __restrict__ sgu_g, const float* __restrict__ sgu_b)
{
    extern __shared__ unsigned sm[];
    unsigned* Bs = sm;
    unsigned* As = sm + 128*68;
    float* rowstat = (float*)(sm + 3*128*68);   // [128][4]
    const int tid = threadIdx.x;
    const int col0 = blockIdx.x * 128;
    const int tbase = blockIdx.y * RT;
    LA_TILE(Bs, Bw + (size_t)col0*128);
    LA_TILE(As, A + (size_t)tbase*128*128);
    CP_COMMIT();
    LA_TILE(As + 128*68, A + (size_t)(tbase + 1)*128*128);
    CP_COMMIT();
    WARP_DECLS
#pragma unroll 1
    for (int t = 0; t < RT; t++) {
        if (t == RT - 1) CP_WAIT0(); else CP_WAIT1();
        __syncthreads();
        ACC_DECL
        MAINLOOP_128(As + (t & 1)*128*68, Bs);
        __syncthreads();
        if (t + 2 < RT) {
            LA_TILE(As + (t & 1)*128*68, A + (size_t)(tbase + t + 2)*128*128);
            CP_COMMIT();
        }
        const int row0 = (tbase + t) * 128;
        float sums[2][2] = {{0,0},{0,0}}, sqs[2][2] = {{0,0},{0,0}};
#pragma unroll
        for (int mt = 0; mt < 2; mt++)
#pragma unroll
            for (int i2 = 0; i2 < 2; i2++) {
                int r = row0 + wm*32 + mt*16 + qg + i2*8;
                float c0v = coords[(size_t)r*2], c1v = coords[(size_t)r*2 + 1];
#pragma unroll
                for (int nt = 0; nt < 8; nt++)
#pragma unroll
                    for (int j = 0; j < 2; j++) {
                        int c = col0 + wn*64 + nt*8 + rg*2 + j;
                        float v = acc[mt][nt][i2*2 + j] + b1[c] + c0v*aW[c] + c1v*aW[256 + c] + ab[c];
                        v = fmaxf(v, 0.f);
                        acc[mt][nt][i2*2 + j] = v;
                        sums[mt][i2] += v;
                        sqs[mt][i2]  += v * v;
                    }
            }
        if (col0 == 0) {
#pragma unroll
            for (int mt = 0; mt < 2; mt++)
#pragma unroll
                for (int i2 = 0; i2 < 2; i2++) {
                    int r = row0 + wm*32 + mt*16 + qg + i2*8;
#pragma unroll
                    for (int nt = 0; nt < 8; nt++) {
                        int c = wn*64 + nt*8 + rg*2;
                        *(__half2*)(u + (size_t)r*128 + c) =
                            __floats2half2_rn(acc[mt][nt][i2*2], acc[mt][nt][i2*2 + 1]);
                    }
                }
        } else {
#pragma unroll
            for (int mt = 0; mt < 2; mt++)
#pragma unroll
                for (int i2 = 0; i2 < 2; i2++) {
                    float s = sums[mt][i2], q = sqs[mt][i2];
                    s += __shfl_xor_sync(0xffffffffu, s, 1);
                    s += __shfl_xor_sync(0xffffffffu, s, 2);
                    q += __shfl_xor_sync(0xffffffffu, q, 1);
                    q += __shfl_xor_sync(0xffffffffu, q, 2);
                    if (rg == 0) {
                        int rl = wm*32 + mt*16 + qg + i2*8;
                        rowstat[rl*4 + wn*2 + 0] = s;
                        rowstat[rl*4 + wn*2 + 1] = q;
                    }
                }
            __syncthreads();
#pragma unroll
            for (int mt = 0; mt < 2; mt++)
#pragma unroll
                for (int i2 = 0; i2 < 2; i2++) {
                    int rl = wm*32 + mt*16 + qg + i2*8;
                    int r = row0 + rl;
                    float s = rowstat[rl*4] + rowstat[rl*4 + 2];
                    float q = rowstat[rl*4 + 1] + rowstat[rl*4 + 3];
                    float mean = s * (1.f/128.f);
                    float var  = q * (1.f/128.f) - mean * mean;
                    float rinv = rsqrtf(var + 1e-5f);
                    int bt = r / NN, node = r - bt * NN;
#pragma unroll
                    for (int nt = 0; nt < 8; nt++)
#pragma unroll
                        for (int j = 0; j < 2; j++) {
                            int f = wn*64 + nt*8 + rg*2 + j;
                            float v = (acc[mt][nt][i2*2 + j] - mean) * rinv * sgu_g[f] + sgu_b[f];
                            vnT[((size_t)bt*130 + f + 1)*384 + node] = __float2half_rn(v);
                        }
                }
            __syncthreads();   // rowstat reuse safety across tiles
        }
    }
}

// ---------------- flash attention: grid (3, BT); warp owns 16 q-rows ----
__global__ __launch_bounds__(256)
void attn_kernel(const __half* __restrict__ qkvh, __half* __restrict__ attnout)
{
    extern __shared__ unsigned sm[];
    unsigned* qs = sm;              // [128][68]
    unsigned* ks = sm + 128*68;     // [64][68]
    unsigned* vs = ks + 64*68;      // [64][68]
    unsigned* Pb = vs + 64*68;      // [128][36]
    const int bt = blockIdx.y, q0 = blockIdx.x * 128;
    const int tid = threadIdx.x;
    const __half* base = qkvh + (size_t)bt * NN * 384;

#pragma unroll
    for (int i = 0; i < 8; i++) {
        int lin = tid + 256*i; int r = lin >> 4, ch = lin & 15;
        int gr = min(q0 + r, NN - 1); bool p = (q0 + r) < NN;
        cp16(sptr(qs + r*68 + ch*4), base + (size_t)gr*384 + ch*8, p);
    }
#define LKV(c0) do {                                                         \
        _Pragma("unroll")                                                    \
        for (int i = 0; i < 4; i++) {                                        \
            int lin = tid + 256*i; int r = lin >> 4, ch = lin & 15;          \
            int gr = min((c0) + r, NN - 1); bool p = ((c0) + r) < NN;        \
            cp16(sptr(ks + r*68 + ch*4), base + (size_t)gr*384 + 128 + ch*8, p); \
            cp16(sptr(vs + r*68 + ch*4), base + (size_t)gr*384 + 256 + ch*8, p); \
        }                                                                    \
    } while (0)
    LKV(0);
    CP_COMMIT(); CP_WAIT0(); __syncthreads();

    const int lane = tid & 31, wid = tid >> 5;
    const int qg = lane >> 2, rg = lane & 3;
    const int R = wid * 16;
    float Oacc[16][4];
#pragma unroll
    for (int a_=0;a_<16;a_++)
#pragma unroll
        for (int c_=0;c_<4;c_++) Oacc[a_][c_] = 0.f;
    float lacc[2] = {0.f, 0.f};

    const unsigned qaddr  = sptr(qs + (R + (lane & 15))*68 + ((lane >> 4) << 2));
    const unsigned paddrA = sptr(Pb + (R + (lane & 15))*36 + ((lane >> 4) << 2));
    unsigned kaddr[4], vaddr[8];
#pragma unroll
    for (int p = 0; p < 4; p++)
        kaddr[p] = sptr(ks + (p*16 + (lane & 7) + ((lane >> 4) << 3))*68 + (((lane >> 3) & 1) << 2));
#pragma unroll
    for (int p = 0; p < 8; p++)
        vaddr[p] = sptr(vs + ((lane & 7) + ((lane & 8) ? 8 : 0))*68 + p*8 + ((lane >> 4) << 2));

    for (int it = 0; it < 6; it++) {
        const int c0 = it * 64;
        float S[8][4];
#pragma unroll
        for (int a_=0;a_<8;a_++)
#pragma unroll
            for (int c_=0;c_<4;c_++) S[a_][c_] = 0.f;
#pragma unroll
        for (int s = 0; s < 8; s++) {
            unsigned a[4], b[4];
            ldsm4(a, qaddr + s*32);
#pragma unroll
            for (int p = 0; p < 4; p++) {
                ldsm4(b, kaddr[p] + s*32);
                mma_f16(S[2*p],     a, b[0], b[1]);
                mma_f16(S[2*p + 1], a, b[2], b[3]);
            }
        }
        float rs[2] = {0.f, 0.f};
#pragma unroll
        for (int ntl = 0; ntl < 8; ntl++)
#pragma unroll
            for (int i2 = 0; i2 < 2; i2++) {
                int colb = c0 + ntl*8 + rg*2;
                float p0 = (colb     < NN) ? __expf(S[ntl][i2*2])     : 0.f;
                float p1 = (colb + 1 < NN) ? __expf(S[ntl][i2*2 + 1]) : 0.f;
                __half2 hp = __floats2half2_rn(p0, p1);
                rs[i2] += __half2float(__low2half(hp)) + __half2float(__high2half(hp));
                Pb[(R + qg + i2*8)*36 + ntl*4 + rg] = h2u(hp);
            }
#pragma unroll
        for (int i2 = 0; i2 < 2; i2++) {
            rs[i2] += __shfl_xor_sync(0xffffffffu, rs[i2], 1);
            rs[i2] += __shfl_xor_sync(0xffffffffu, rs[i2], 2);
            lacc[i2] += rs[i2];
        }
        __syncwarp();
#pragma unroll
        for (int s = 0; s < 4; s++) {
            unsigned a[4], b[4];
            ldsm4(a, paddrA + s*32);
#pragma unroll
            for (int p = 0; p < 8; p++) {
                ldsm4t(b, vaddr[p] + s*(16*68*4));
                mma_f16(Oacc[2*p],     a, b[0], b[1]);
                mma_f16(Oacc[2*p + 1], a, b[2], b[3]);
            }
        }
        __syncthreads();
        if (it < 5) {
            LKV((it + 1) * 64);
            CP_COMMIT(); CP_WAIT0(); __syncthreads();
        }
    }
#undef LKV
#pragma unroll
    for (int i2 = 0; i2 < 2; i2++) {
        int n = q0 + R + qg + i2*8;
        if (n >= NN) continue;
        float inv = 1.f / lacc[i2];
        __half* orow = attnout + ((size_t)bt * NN + n) * 128;
#pragma unroll
        for (int ng = 0; ng < 16; ng++) {
            int f = ng*8 + rg*2;
            *(__half2*)(orow + f) =
                __floats2half2_rn(Oacc[ng][i2*2] * inv, Oacc[ng][i2*2 + 1] * inv);
        }
    }
}

// ---------------- conv: A=cwt[tap][n][m], B=vnT rows (tap = row shift) --
__global__ __launch_bounds__(256)
void conv_tc(const __half* __restrict__ cwt, const __half* __restrict__ vnT,
             const float* __restrict__ cb, const float* __restrict__ gres,
             const __half* __restrict__ u, __half* __restrict__ sg)
{
    extern __shared__ unsigned sm[];
    unsigned* As = sm;             // [128][68]  cwt rows n, cols m-chunk
    unsigned* Bs = sm + 128*68;    // [130][68]  vnT rows f(+1), cols m-chunk
    const int bt = blockIdx.y, n0 = blockIdx.x * 128;
    const int tid = threadIdx.x;
    const __half* vb = vnT + (size_t)bt * 130 * 384;
    WARP_DECLS
    ACC_DECL

    unsigned aaddr[2], baddr[4];
#pragma unroll
    for (int mt = 0; mt < 2; mt++)
        aaddr[mt] = sptr(As + (wm*32 + mt*16 + (lane & 15))*68 + ((lane >> 4) << 2));
#pragma unroll
    for (int p = 0; p < 4; p++)
        baddr[p] = sptr(Bs + (wn*64 + p*16 + (lane & 7) + ((lane >> 4) << 3))*68 + (((lane >> 3) & 1) << 2));

    for (int mc = 0; mc < 3; mc++) {
        for (int tap = 0; tap < 3; tap++) {
            if (mc || tap) __syncthreads();
            if (tap == 0) {
#pragma unroll
                for (int i = 0; i < 9; i++) {
                    int lin = tid + 256*i;
                    if (lin < 2080) {
                        int r = lin >> 4, ch = lin & 15;
                        cp16(sptr(Bs + r*68 + ch*4),
                             vb + (size_t)r*384 + mc*128 + ch*8, true);
                    }
                }
            }
#pragma unroll
            for (int i = 0; i < 8; i++) {
                int lin = tid + 256*i; int r = lin >> 4, ch = lin & 15;
                cp16(sptr(As + r*68 + ch*4),
                     cwt + ((size_t)tap*384 + n0 + r)*384 + mc*128 + ch*8, true);
            }
            CP_COMMIT(); CP_WAIT0(); __syncthreads();
            const int toff = tap * 272;   // tap rows of Bs in bytes (68*4)
#pragma unroll
            for (int s = 0; s < 8; s++) {
                unsigned a[2][4], b[4][4];
#pragma unroll
                for (int mt = 0; mt < 2; mt++) ldsm4(a[mt], aaddr[mt] + s*32);
#pragma unroll
                for (int p = 0; p < 4; p++) ldsm4(b[p], baddr[p] + toff + s*32);
#pragma unroll
                for (int mt = 0; mt < 2; mt++)
#pragma unroll
                    for (int p = 0; p < 4; p++) {
                        mma_f16(acc[mt][2*p],     a[mt], b[p][0], b[p][1]);
                        mma_f16(acc[mt][2*p + 1], a[mt], b[p][2], b[p][3]);
                    }
            }
        }
    }
#pragma unroll
    for (int mt = 0; mt < 2; mt++)
#pragma unroll
        for (int i2 = 0; i2 < 2; i2++) {
            int n = n0 + wm*32 + mt*16 + qg + i2*8;
            if (n >= NN) continue;
            size_t row = (size_t)bt * NN + n;
            float bias = cb[n];
#pragma unroll
            for (int nt = 0; nt < 8; nt++) {
                int f = wn*64 + nt*8 + rg*2;
                __half2 uh = *(const __half2*)(u + row*128 + f);
                float v0 = (acc[mt][nt][i2*2]     + bias + gres[row*128 + f])     * __half2float(__low2half(uh));
                float v1 = (acc[mt][nt][i2*2 + 1] + bias + gres[row*128 + f + 1]) * __half2float(__high2half(uh));
                *(__half2*)(sg + row*128 + f) = __floats2half2_rn(v0, v1);
            }
        }
}

// ---------------- host launcher ----------------
extern "C" void kernel_launch(void* const* d_in, const int* in_sizes, int n_in,
                              void* d_out, int out_size)
{
    const float* x      = (const float*)d_in[0];
    const float* norm_g = (const float*)d_in[1];
    const float* norm_b = (const float*)d_in[2];
    const float* W1     = (const float*)d_in[3];
    const float* b1     = (const float*)d_in[4];
    const float* aff1_W = (const float*)d_in[5];
    const float* aff1_b = (const float*)d_in[6];
    const float* Wl     = (const float*)d_in[7];
    const float* bl     = (const float*)d_in[8];
    const float* sgu_g  = (const float*)d_in[9];
    const float* sgu_b  = (const float*)d_in[10];
    const float* conv_w = (const float*)d_in[11];
    const float* conv_b = (const float*)d_in[12];
    const float* Wqkv   = (const float*)d_in[13];
    const float* bqkv   = (const float*)d_in[14];
    const float* Wo     = (const float*)d_in[15];
    const float* bo     = (const float*)d_in[16];
    const float* W2     = (const float*)d_in[17];
    const float* b2     = (const float*)d_in[18];
    float* out = (float*)d_out;

    __half *xn, *qkvh, *vnT, *attnout, *sg, *wqkv, *w1, *wo, *w2, *cwt, *uu;
    float *coords, *gateres;
    cudaGetSymbolAddress((void**)&xn,      g_xn);
    cudaGetSymbolAddress((void**)&qkvh,    g_qkvh);
    cudaGetSymbolAddress((void**)&coords,  g_coords);
    cudaGetSymbolAddress((void**)&uu,      g_u);
    cudaGetSymbolAddress((void**)&vnT,     g_vnT);
    cudaGetSymbolAddress((void**)&attnout, g_attnout);
    cudaGetSymbolAddress((void**)&gateres, g_gateres);
    cudaGetSymbolAddress((void**)&sg,      g_sg);
    cudaGetSymbolAddress((void**)&wqkv,    g_wqkv);
    cudaGetSymbolAddress((void**)&w1,      g_w1);
    cudaGetSymbolAddress((void**)&wo,      g_wo);
    cudaGetSymbolAddress((void**)&w2,      g_w2);
    cudaGetSymbolAddress((void**)&cwt,     g_cwt);

    const int GEMM_SMEM = (3*128*68) * 4;                       // 104448
    const int FC1_SMEM  = GEMM_SMEM + 2048;                     // 106496
    const int ATTN_SMEM = (128*68 + 2*64*68 + 128*36) * 4;      // 88064
    const int CONV_SMEM = (128*68 + 130*68) * 4;                // 70176
    static bool attr_done = false;
    if (!attr_done) {
        cudaFuncSetAttribute(gemm_h<0>,   cudaFuncAttributeMaxDynamicSharedMemorySize, GEMM_SMEM);
        cudaFuncSetAttribute(gemm_h<1>,   cudaFuncAttributeMaxDynamicSharedMemorySize, GEMM_SMEM);
        cudaFuncSetAttribute(gemm_h<2>,   cudaFuncAttributeMaxDynamicSharedMemorySize, GEMM_SMEM);
        cudaFuncSetAttribute(fc1_kernel,  cudaFuncAttributeMaxDynamicSharedMemorySize, FC1_SMEM);
        cudaFuncSetAttribute(attn_kernel, cudaFuncAttributeMaxDynamicSharedMemorySize, ATTN_SMEM);
        cudaFuncSetAttribute(conv_tc,     cudaFuncAttributeMaxDynamicSharedMemorySize, CONV_SMEM);
        attr_done = true;
    }

    // 0) weights -> half (transposed / padded)
    prep_kernel<<<1687, 256>>>(Wqkv, W1, Wo, W2, conv_w, wqkv, w1, wo, w2, cwt);
    // 1) LN(x) -> xn half + coords
    ln_kernel<<<(MT + 7) / 8, 256>>>(x, xn, norm_g, norm_b, coords, Wl, bl);
    // 2) qkv = xn @ Wqkv + bqkv -> qkvh half [row][384]
    {
        dim3 g(3, 325);
        gemm_h<0><<<g, 256, GEMM_SMEM>>>(xn, wqkv, qkvh, bqkv, nullptr);
    }
    // 3) FC1 + fused SGU-LN -> u (half), vnT (half, transposed)
    {
        dim3 g(2, 325);
        fc1_kernel<<<g, 256, FC1_SMEM>>>(xn, w1, uu, vnT, coords,
                                         b1, aff1_W, aff1_b, sgu_g, sgu_b);
    }
    // 4) fused attention -> attnout (half)
    {
        dim3 g(3, BT);
        attn_kernel<<<g, 256, ATTN_SMEM>>>(qkvh, attnout);
    }
    // 5) gate_res = attnout @ Wo + bo (float)
    {
        dim3 g(1, 325);
        gemm_h<1><<<g, 256, GEMM_SMEM>>>(attnout, wo, gateres, bo, nullptr);
    }
    // 6) conv + gate -> sg (half)
    {
        dim3 g(3, BT);
        conv_tc<<<g, 256, CONV_SMEM>>>(cwt, vnT, conv_b, gateres, uu, sg);
    }
    // 7) out = relu(sg @ W2 + b2) + x
    {
        dim3 g(1, 325);
        gemm_h<2><<<g, 256, GEMM_SMEM>>>(sg, w2, out, b2, x);
    }
}

// round 15
// speedup vs baseline: 1.1042x; 1.1042x over previous
#include <cuda_runtime.h>
#include <cuda_fp16.h>
#include <cstdint>

#define BT 384
#define NN 325
#define MT (BT*NN)     // 124800

// ---------------- scratch (device globals; zero-initialized) -----------
__device__ __half g_xn     [(size_t)MT*128];
__device__ __half g_qkvh   [(size_t)MT*384];
__device__ float  g_coords [(size_t)MT*2];
__device__ __half g_u      [(size_t)MT*128];
__device__ __half g_vnT    [(size_t)BT*130*384];  // rows 0 and 129 stay zero
__device__ __half g_gateres[(size_t)MT*128];
__device__ __half g_sg     [(size_t)MT*128];
__device__ __half g_wqkv   [384*128];
__device__ __half g_w1     [256*128];
__device__ __half g_wo     [128*128];
__device__ __half g_w2     [128*128];
__device__ __half g_cwt    [3*384*384];           // [tap][n pad384][m pad384]

// ---------------- helpers ----------------
__device__ __forceinline__ unsigned sptr(const void* p) {
    return (unsigned)__cvta_generic_to_shared(p);
}
__device__ __forceinline__ void cp16(unsigned dst, const void* src, bool pred) {
    int sz = pred ? 16 : 0;
    asm volatile("cp.async.ca.shared.global [%0], [%1], 16, %2;\n"
                 :: "r"(dst), "l"(src), "r"(sz));
}
#define CP_COMMIT() asm volatile("cp.async.commit_group;\n")
#define CP_WAIT0()  asm volatile("cp.async.wait_group 0;\n")

__device__ __forceinline__ void ldsm4(unsigned* r, unsigned addr) {
    asm volatile("ldmatrix.sync.aligned.m8n8.x4.shared.b16 {%0,%1,%2,%3}, [%4];\n"
                 : "=r"(r[0]), "=r"(r[1]), "=r"(r[2]), "=r"(r[3]) : "r"(addr));
}
__device__ __forceinline__ void ldsm4t(unsigned* r, unsigned addr) {
    asm volatile("ldmatrix.sync.aligned.m8n8.x4.trans.shared.b16 {%0,%1,%2,%3}, [%4];\n"
                 : "=r"(r[0]), "=r"(r[1]), "=r"(r[2]), "=r"(r[3]) : "r"(addr));
}
__device__ __forceinline__ void mma_f16(float* c, const unsigned* a, unsigned b0, unsigned b1) {
    asm volatile("mma.sync.aligned.m16n8k16.row.col.f32.f16.f16.f32 "
                 "{%0,%1,%2,%3}, {%4,%5,%6,%7}, {%8,%9}, {%0,%1,%2,%3};\n"
                 : "+f"(c[0]), "+f"(c[1]), "+f"(c[2]), "+f"(c[3])
                 : "r"(a[0]), "r"(a[1]), "r"(a[2]), "r"(a[3]), "r"(b0), "r"(b1));
}
__device__ __forceinline__ unsigned h2u(__half2 h) {
    unsigned u; memcpy(&u, &h, 4); return u;
}

// ---------------- prep: weights -> half, transposed --------------------
__global__ __launch_bounds__(256)
void prep_kernel(const float* __restrict__ Wqkv, const float* __restrict__ W1,
                 const float* __restrict__ Wo, const float* __restrict__ W2,
                 const float* __restrict__ cw,
                 __half* __restrict__ oq, __half* __restrict__ o1,
                 __half* __restrict__ oo, __half* __restrict__ o2,
                 __half* __restrict__ ocw)
{
    int i = blockIdx.x * 256 + threadIdx.x;
    if (i < 49152) { int n = i >> 7, k = i & 127;
        oq[n*128 + k] = __float2half_rn(Wqkv[(size_t)k*384 + n]); return; }
    i -= 49152;
    if (i < 32768) { int n = i >> 7, k = i & 127;
        o1[n*128 + k] = __float2half_rn(W1[(size_t)k*256 + n]); return; }
    i -= 32768;
    if (i < 16384) { int n = i >> 7, k = i & 127;
        oo[n*128 + k] = __float2half_rn(Wo[(size_t)k*128 + n]); return; }
    i -= 16384;
    if (i < 16384) { int n = i >> 7, k = i & 127;
        o2[n*128 + k] = __float2half_rn(W2[(size_t)k*128 + n]); return; }
    i -= 16384;
    if (i < 316875) {   // 3*325*325
        int t = i / 105625, rem = i % 105625;
        int n = rem / 325, m = rem % 325;
        ocw[(size_t)t*384*384 + n*384 + m] =
            __float2half_rn(cw[((size_t)n*325 + m)*3 + t]);
    }
}

// ---------------- LayerNorm(x) -> xn half + coords fp32 ----------------
__global__ __launch_bounds__(256)
void ln_kernel(const float* __restrict__ in, __half* __restrict__ out,
               const float* __restrict__ gam, const float* __restrict__ bet,
               float* __restrict__ coords,
               const float* __restrict__ Wl, const float* __restrict__ bl)
{
    int row = blockIdx.x * 8 + (threadIdx.x >> 5);
    if (row >= MT) return;
    int lane = threadIdx.x & 31;
    float4 v = *(const float4*)(in + (size_t)row * 128 + lane * 4);
    float s  = v.x + v.y + v.z + v.w;
    float ss = v.x*v.x + v.y*v.y + v.z*v.z + v.w*v.w;
#pragma unroll
    for (int o = 16; o > 0; o >>= 1) {
        s  += __shfl_xor_sync(0xffffffffu, s,  o);
        ss += __shfl_xor_sync(0xffffffffu, ss, o);
    }
    float mean = s * (1.f/128.f);
    float var  = ss * (1.f/128.f) - mean * mean;
    float r = rsqrtf(var + 1e-5f);
    int c = lane * 4;
    float o0 = (v.x - mean) * r * gam[c+0] + bet[c+0];
    float o1 = (v.y - mean) * r * gam[c+1] + bet[c+1];
    float o2 = (v.z - mean) * r * gam[c+2] + bet[c+2];
    float o3 = (v.w - mean) * r * gam[c+3] + bet[c+3];
    __half2* orow = (__half2*)(out + (size_t)row * 128);
    orow[lane*2]     = __floats2half2_rn(o0, o1);
    orow[lane*2 + 1] = __floats2half2_rn(o2, o3);
    float c0 = o0*Wl[(c+0)*2] + o1*Wl[(c+1)*2] + o2*Wl[(c+2)*2] + o3*Wl[(c+3)*2];
    float c1 = o0*Wl[(c+0)*2+1] + o1*Wl[(c+1)*2+1] + o2*Wl[(c+2)*2+1] + o3*Wl[(c+3)*2+1];
#pragma unroll
    for (int o = 16; o > 0; o >>= 1) {
        c0 += __shfl_xor_sync(0xffffffffu, c0, o);
        c1 += __shfl_xor_sync(0xffffffffu, c1, o);
    }
    if (lane == 0) {
        coords[(size_t)row*2 + 0] = c0 + bl[0];
        coords[(size_t)row*2 + 1] = c1 + bl[1];
    }
}

// ======== common pieces (tiles: rows of 128 halves = 64 u32, stride 68) =
#define WARP_DECLS \
    const int lane = tid & 31, wid = tid >> 5; \
    const int wm = wid >> 1, wn = wid & 1;     \
    const int qg = lane >> 2, rg = lane & 3;

#define MAINLOOP_128(As, Bs) do {                                            \
    unsigned aaddr[2], baddr[4];                                             \
    _Pragma("unroll")                                                        \
    for (int mt = 0; mt < 2; mt++)                                           \
        aaddr[mt] = sptr((As) + (wm*32 + mt*16 + (lane & 15))*68 + ((lane >> 4) << 2)); \
    _Pragma("unroll")                                                        \
    for (int p = 0; p < 4; p++)                                              \
        baddr[p] = sptr((Bs) + (wn*64 + p*16 + (lane & 7) + ((lane >> 4) << 3))*68 + (((lane >> 3) & 1) << 2)); \
    _Pragma("unroll")                                                        \
    for (int s = 0; s < 8; s++) {                                            \
        unsigned a[2][4], b[4][4];                                           \
        _Pragma("unroll")                                                    \
        for (int mt = 0; mt < 2; mt++) ldsm4(a[mt], aaddr[mt] + s*32);       \
        _Pragma("unroll")                                                    \
        for (int p = 0; p < 4; p++) ldsm4(b[p], baddr[p] + s*32);            \
        _Pragma("unroll")                                                    \
        for (int mt = 0; mt < 2; mt++)                                       \
            _Pragma("unroll")                                                \
            for (int p = 0; p < 4; p++) {                                    \
                mma_f16(acc[mt][2*p],     a[mt], b[p][0], b[p][1]);          \
                mma_f16(acc[mt][2*p + 1], a[mt], b[p][2], b[p][3]);          \
            }                                                                \
    }                                                                        \
} while (0)

#define LOAD_AB_128(As, Bs, Aptr, Bptr) do {                                 \
    _Pragma("unroll")                                                        \
    for (int i = 0; i < 8; i++) {                                            \
        int lin = tid + 256*i; int r = lin >> 4, ch = lin & 15;              \
        cp16(sptr((As) + r*68 + ch*4), (Aptr) + (size_t)r*128 + ch*8, true); \
    }                                                                        \
    _Pragma("unroll")                                                        \
    for (int i = 0; i < 8; i++) {                                            \
        int lin = tid + 256*i; int r = lin >> 4, ch = lin & 15;              \
        cp16(sptr((Bs) + r*68 + ch*4), (Bptr) + (size_t)r*128 + ch*8, true); \
    }                                                                        \
    CP_COMMIT(); CP_WAIT0(); __syncthreads();                                \
} while (0)

#define ACC_DECL float acc[2][8][4];                                         \
    _Pragma("unroll") for (int a_=0;a_<2;a_++)                               \
    _Pragma("unroll") for (int b_=0;b_<8;b_++)                               \
    _Pragma("unroll") for (int c_=0;c_<4;c_++) acc[a_][b_][c_] = 0.f;

// ---------------- dense GEMM (M=MT, K=128), round-8 shape ---------------
// EPI: 0 = +bias -> half [row][384] ; 2 = +bias, relu, +res -> float[128]
template<int EPI>
__global__ __launch_bounds__(256)
void gemm_h(const __half* __restrict__ A, const __half* __restrict__ Bw,
            void* __restrict__ Cout, const float* __restrict__ bias,
            const float* __restrict__ res)
{
    extern __shared__ unsigned sm[];
    unsigned* As = sm;             // [128][68]
    unsigned* Bs = sm + 128*68;    // [128][68]
    const int tid = threadIdx.x;
    const int row0 = blockIdx.y * 128, col0 = blockIdx.x * 128;
    LOAD_AB_128(As, Bs, A + (size_t)row0*128, Bw + (size_t)col0*128);
    WARP_DECLS
    ACC_DECL
    MAINLOOP_128(As, Bs);
#pragma unroll
    for (int mt = 0; mt < 2; mt++)
#pragma unroll
        for (int i2 = 0; i2 < 2; i2++) {
            int r = row0 + wm*32 + mt*16 + qg + i2*8;
#pragma unroll
            for (int nt = 0; nt < 8; nt++) {
                int c = col0 + wn*64 + nt*8 + rg*2;
                float v0 = acc[mt][nt][i2*2]     + bias[c];
                float v1 = acc[mt][nt][i2*2 + 1] + bias[c + 1];
                if (EPI == 0) {
                    *(__half2*)((__half*)Cout + (size_t)r*384 + c) = __floats2half2_rn(v0, v1);
                } else {
                    float* C = (float*)Cout;
                    C[(size_t)r*128 + c]     = fmaxf(v0, 0.f) + res[(size_t)r*128 + c];
                    C[(size_t)r*128 + c + 1] = fmaxf(v1, 0.f) + res[(size_t)r*128 + c + 1];
                }
            }
        }
}

// ---------------- FC1 + fused SGU-LN (u half, vnT half transposed) ------
__global__ __launch_bounds__(256)
void fc1_kernel(const __half* __restrict__ A, const __half* __restrict__ Bw,
                __half* __restrict__ u, __half* __restrict__ vnT,
                const float* __restrict__ coords,
                const float* __restrict__ b1,
                const float* __restrict__ aW, const float* __restrict__ ab,
                const float* __restrict__ sgu_g, const float* __restrict__ sgu_b)
{
    extern __shared__ unsigned sm[];
    unsigned* As = sm;
    unsigned* Bs = sm + 128*68;
    const int tid = threadIdx.x;
    const int row0 = blockIdx.y * 128, col0 = blockIdx.x * 128;
    LOAD_AB_128(As, Bs, A + (size_t)row0*128, Bw + (size_t)col0*128);
    WARP_DECLS
    ACC_DECL
    MAINLOOP_128(As, Bs);
    float sums[2][2] = {{0,0},{0,0}}, sqs[2][2] = {{0,0},{0,0}};
#pragma unroll
    for (int mt = 0; mt < 2; mt++)
#pragma unroll
        for (int i2 = 0; i2 < 2; i2++) {
            int r = row0 + wm*32 + mt*16 + qg + i2*8;
            float c0v = coords[(size_t)r*2], c1v = coords[(size_t)r*2 + 1];
#pragma unroll
            for (int nt = 0; nt < 8; nt++)
#pragma unroll
                for (int j = 0; j < 2; j++) {
                    int c = col0 + wn*64 + nt*8 + rg*2 + j;
                    float v = acc[mt][nt][i2*2 + j] + b1[c] + c0v*aW[c] + c1v*aW[256 + c] + ab[c];
                    v = fmaxf(v, 0.f);
                    acc[mt][nt][i2*2 + j] = v;
                    sums[mt][i2] += v;
                    sqs[mt][i2]  += v * v;
                }
        }
    if (col0 == 0) {
#pragma unroll
        for (int mt = 0; mt < 2; mt++)
#pragma unroll
            for (int i2 = 0; i2 < 2; i2++) {
                int r = row0 + wm*32 + mt*16 + qg + i2*8;
#pragma unroll
                for (int nt = 0; nt < 8; nt++) {
                    int c = wn*64 + nt*8 + rg*2;
                    *(__half2*)(u + (size_t)r*128 + c) =
                        __floats2half2_rn(acc[mt][nt][i2*2], acc[mt][nt][i2*2 + 1]);
                }
            }
    } else {
        float* rowstat = (float*)As;   // reuse smem: [128][4]
        __syncthreads();
#pragma unroll
        for (int mt = 0; mt < 2; mt++)
#pragma unroll
            for (int i2 = 0; i2 < 2; i2++) {
                float s = sums[mt][i2], q = sqs[mt][i2];
                s += __shfl_xor_sync(0xffffffffu, s, 1);
                s += __shfl_xor_sync(0xffffffffu, s, 2);
                q += __shfl_xor_sync(0xffffffffu, q, 1);
                q += __shfl_xor_sync(0xffffffffu, q, 2);
                if (rg == 0) {
                    int rl = wm*32 + mt*16 + qg + i2*8;
                    rowstat[rl*4 + wn*2 + 0] = s;
                    rowstat[rl*4 + wn*2 + 1] = q;
                }
            }
        __syncthreads();
#pragma unroll
        for (int mt = 0; mt < 2; mt++)
#pragma unroll
            for (int i2 = 0; i2 < 2; i2++) {
                int rl = wm*32 + mt*16 + qg + i2*8;
                int r = row0 + rl;
                float s = rowstat[rl*4] + rowstat[rl*4 + 2];
                float q = rowstat[rl*4 + 1] + rowstat[rl*4 + 3];
                float mean = s * (1.f/128.f);
                float var  = q * (1.f/128.f) - mean * mean;
                float rinv = rsqrtf(var + 1e-5f);
                int bt = r / NN, node = r - bt * NN;
#pragma unroll
                for (int nt = 0; nt < 8; nt++)
#pragma unroll
                    for (int j = 0; j < 2; j++) {
                        int f = wn*64 + nt*8 + rg*2 + j;
                        float v = (acc[mt][nt][i2*2 + j] - mean) * rinv * sgu_g[f] + sgu_b[f];
                        vnT[((size_t)bt*130 + f + 1)*384 + node] = __float2half_rn(v);
                    }
            }
    }
}

// ---------------- flash attention + fused Wo: grid (3, BT) --------------
// After the KV loop, O (normalized fp16) is staged in qs, Wo loaded into
// ks+vs (contiguous 128x68), and one more 128-K MMA pass writes
// gateres = O @ Wo + bo directly (fp16).
__global__ __launch_bounds__(256)
void attn_kernel(const __half* __restrict__ qkvh, const __half* __restrict__ wo,
                 const float* __restrict__ bo, __half* __restrict__ gateres)
{
    extern __shared__ unsigned sm[];
    unsigned* qs = sm;              // [128][68]
    unsigned* ks = sm + 128*68;     // [64][68]   (contiguous with vs)
    unsigned* vs = ks + 64*68;      // [64][68]
    unsigned* Pb = vs + 64*68;      // [128][36]
    const int bt = blockIdx.y, q0 = blockIdx.x * 128;
    const int tid = threadIdx.x;
    const __half* base = qkvh + (size_t)bt * NN * 384;

#pragma unroll
    for (int i = 0; i < 8; i++) {
        int lin = tid + 256*i; int r = lin >> 4, ch = lin & 15;
        int gr = min(q0 + r, NN - 1); bool p = (q0 + r) < NN;
        cp16(sptr(qs + r*68 + ch*4), base + (size_t)gr*384 + ch*8, p);
    }
#define LKV(c0) do {                                                         \
        _Pragma("unroll")                                                    \
        for (int i = 0; i < 4; i++) {                                        \
            int lin = tid + 256*i; int r = lin >> 4, ch = lin & 15;          \
            int gr = min((c0) + r, NN - 1); bool p = ((c0) + r) < NN;        \
            cp16(sptr(ks + r*68 + ch*4), base + (size_t)gr*384 + 128 + ch*8, p); \
            cp16(sptr(vs + r*68 + ch*4), base + (size_t)gr*384 + 256 + ch*8, p); \
        }                                                                    \
    } while (0)
    LKV(0);
    CP_COMMIT(); CP_WAIT0(); __syncthreads();

    const int lane = tid & 31, wid = tid >> 5;
    const int qg = lane >> 2, rg = lane & 3;
    const int R = wid * 16;
    float Oacc[16][4];
#pragma unroll
    for (int a_=0;a_<16;a_++)
#pragma unroll
        for (int c_=0;c_<4;c_++) Oacc[a_][c_] = 0.f;
    float lacc[2] = {0.f, 0.f};

    const unsigned qaddr  = sptr(qs + (R + (lane & 15))*68 + ((lane >> 4) << 2));
    const unsigned paddrA = sptr(Pb + (R + (lane & 15))*36 + ((lane >> 4) << 2));
    unsigned kaddr[4], vaddr[8];
#pragma unroll
    for (int p = 0; p < 4; p++)
        kaddr[p] = sptr(ks + (p*16 + (lane & 7) + ((lane >> 4) << 3))*68 + (((lane >> 3) & 1) << 2));
#pragma unroll
    for (int p = 0; p < 8; p++)
        vaddr[p] = sptr(vs + ((lane & 7) + ((lane & 8) ? 8 : 0))*68 + p*8 + ((lane >> 4) << 2));

    for (int it = 0; it < 6; it++) {
        const int c0 = it * 64;
        float S[8][4];
#pragma unroll
        for (int a_=0;a_<8;a_++)
#pragma unroll
            for (int c_=0;c_<4;c_++) S[a_][c_] = 0.f;
#pragma unroll
        for (int s = 0; s < 8; s++) {
            unsigned a[4], b[4];
            ldsm4(a, qaddr + s*32);
#pragma unroll
            for (int p = 0; p < 4; p++) {
                ldsm4(b, kaddr[p] + s*32);
                mma_f16(S[2*p],     a, b[0], b[1]);
                mma_f16(S[2*p + 1], a, b[2], b[3]);
            }
        }
        float rs[2] = {0.f, 0.f};
#pragma unroll
        for (int ntl = 0; ntl < 8; ntl++)
#pragma unroll
            for (int i2 = 0; i2 < 2; i2++) {
                int colb = c0 + ntl*8 + rg*2;
                float p0 = (colb     < NN) ? __expf(S[ntl][i2*2])     : 0.f;
                float p1 = (colb + 1 < NN) ? __expf(S[ntl][i2*2 + 1]) : 0.f;
                __half2 hp = __floats2half2_rn(p0, p1);
                rs[i2] += __half2float(__low2half(hp)) + __half2float(__high2half(hp));
                Pb[(R + qg + i2*8)*36 + ntl*4 + rg] = h2u(hp);
            }
#pragma unroll
        for (int i2 = 0; i2 < 2; i2++) {
            rs[i2] += __shfl_xor_sync(0xffffffffu, rs[i2], 1);
            rs[i2] += __shfl_xor_sync(0xffffffffu, rs[i2], 2);
            lacc[i2] += rs[i2];
        }
        __syncwarp();
#pragma unroll
        for (int s = 0; s < 4; s++) {
            unsigned a[4], b[4];
            ldsm4(a, paddrA + s*32);
#pragma unroll
            for (int p = 0; p < 8; p++) {
                ldsm4t(b, vaddr[p] + s*(16*68*4));
                mma_f16(Oacc[2*p],     a, b[0], b[1]);
                mma_f16(Oacc[2*p + 1], a, b[2], b[3]);
            }
        }
        __syncthreads();
        if (it < 5) {
            LKV((it + 1) * 64);
            CP_COMMIT(); CP_WAIT0(); __syncthreads();
        }
    }
#undef LKV

    // ---- stage normalized O (fp16) into qs; load Wo into ks/vs ----
#pragma unroll
    for (int i2 = 0; i2 < 2; i2++) {
        int rl = R + qg + i2*8;
        float inv = 1.f / lacc[i2];
#pragma unroll
        for (int ng = 0; ng < 16; ng++) {
            __half2 h = __floats2half2_rn(Oacc[ng][i2*2] * inv,
                                          Oacc[ng][i2*2 + 1] * inv);
            qs[rl*68 + ng*4 + rg] = h2u(h);
        }
    }
#pragma unroll
    for (int i = 0; i < 8; i++) {
        int lin = tid + 256*i; int r = lin >> 4, ch = lin & 15;
        cp16(sptr(ks + r*68 + ch*4), wo + (size_t)r*128 + ch*8, true);
    }
    CP_COMMIT(); CP_WAIT0(); __syncthreads();

    // ---- gateres = O @ Wo + bo ----
    float acc2[16][4];
#pragma unroll
    for (int a_=0;a_<16;a_++)
#pragma unroll
        for (int c_=0;c_<4;c_++) acc2[a_][c_] = 0.f;
    unsigned waddr[8];
#pragma unroll
    for (int p = 0; p < 8; p++)
        waddr[p] = sptr(ks + (p*16 + (lane & 7) + ((lane >> 4) << 3))*68 + (((lane >> 3) & 1) << 2));
#pragma unroll
    for (int s = 0; s < 8; s++) {
        unsigned a[4], b[4];
        ldsm4(a, qaddr + s*32);
#pragma unroll
        for (int p = 0; p < 8; p++) {
            ldsm4(b, waddr[p] + s*32);
            mma_f16(acc2[2*p],     a, b[0], b[1]);
            mma_f16(acc2[2*p + 1], a, b[2], b[3]);
        }
    }
#pragma unroll
    for (int i2 = 0; i2 < 2; i2++) {
        int n = q0 + R + qg + i2*8;
        if (n >= NN) continue;
        __half* grow = gateres + ((size_t)bt * NN + n) * 128;
#pragma unroll
        for (int nt = 0; nt < 16; nt++) {
            int c = nt*8 + rg*2;
            *(__half2*)(grow + c) =
                __floats2half2_rn(acc2[nt][i2*2]     + bo[c],
                                  acc2[nt][i2*2 + 1] + bo[c + 1]);
        }
    }
}

// ---------------- conv: A=cwt[tap][n][m], B=vnT rows (tap = row shift) --
__global__ __launch_bounds__(256)
void conv_tc(const __half* __restrict__ cwt, const __half* __restrict__ vnT,
             const float* __restrict__ cb, const __half* __restrict__ gres,
             const __half* __restrict__ u, __half* __restrict__ sg)
{
    extern __shared__ unsigned sm[];
    unsigned* As = sm;             // [128][68]  cwt rows n, cols m-chunk
    unsigned* Bs = sm + 128*68;    // [130][68]  vnT rows f(+1), cols m-chunk
    const int bt = blockIdx.y, n0 = blockIdx.x * 128;
    const int tid = threadIdx.x;
    const __half* vb = vnT + (size_t)bt * 130 * 384;
    WARP_DECLS
    ACC_DECL

    unsigned aaddr[2], baddr[4];
#pragma unroll
    for (int mt = 0; mt < 2; mt++)
        aaddr[mt] = sptr(As + (wm*32 + mt*16 + (lane & 15))*68 + ((lane >> 4) << 2));
#pragma unroll
    for (int p = 0; p < 4; p++)
        baddr[p] = sptr(Bs + (wn*64 + p*16 + (lane & 7) + ((lane >> 4) << 3))*68 + (((lane >> 3) & 1) << 2));

    for (int mc = 0; mc < 3; mc++) {
        for (int tap = 0; tap < 3; tap++) {
            if (mc || tap) __syncthreads();
            if (tap == 0) {
#pragma unroll
                for (int i = 0; i < 9; i++) {
                    int lin = tid + 256*i;
                    if (lin < 2080) {
                        int r = lin >> 4, ch = lin & 15;
                        cp16(sptr(Bs + r*68 + ch*4),
                             vb + (size_t)r*384 + mc*128 + ch*8, true);
                    }
                }
            }
#pragma unroll
            for (int i = 0; i < 8; i++) {
                int lin = tid + 256*i; int r = lin >> 4, ch = lin & 15;
                cp16(sptr(As + r*68 + ch*4),
                     cwt + ((size_t)tap*384 + n0 + r)*384 + mc*128 + ch*8, true);
            }
            CP_COMMIT(); CP_WAIT0(); __syncthreads();
            const int toff = tap * 272;   // tap rows of Bs in bytes (68*4)
#pragma unroll
            for (int s = 0; s < 8; s++) {
                unsigned a[2][4], b[4][4];
#pragma unroll
                for (int mt = 0; mt < 2; mt++) ldsm4(a[mt], aaddr[mt] + s*32);
#pragma unroll
                for (int p = 0; p < 4; p++) ldsm4(b[p], baddr[p] + toff + s*32);
#pragma unroll
                for (int mt = 0; mt < 2; mt++)
#pragma unroll
                    for (int p = 0; p < 4; p++) {
                        mma_f16(acc[mt][2*p],     a[mt], b[p][0], b[p][1]);
                        mma_f16(acc[mt][2*p + 1], a[mt], b[p][2], b[p][3]);
                    }
            }
        }
    }
#pragma unroll
    for (int mt = 0; mt < 2; mt++)
#pragma unroll
        for (int i2 = 0; i2 < 2; i2++) {
            int n = n0 + wm*32 + mt*16 + qg + i2*8;
            if (n >= NN) continue;
            size_t row = (size_t)bt * NN + n;
            float bias = cb[n];
#pragma unroll
            for (int nt = 0; nt < 8; nt++) {
                int f = wn*64 + nt*8 + rg*2;
                __half2 gh = *(const __half2*)(gres + row*128 + f);
                __half2 uh = *(const __half2*)(u + row*128 + f);
                float v0 = (acc[mt][nt][i2*2]     + bias + __half2float(__low2half(gh)))
                         * __half2float(__low2half(uh));
                float v1 = (acc[mt][nt][i2*2 + 1] + bias + __half2float(__high2half(gh)))
                         * __half2float(__high2half(uh));
                *(__half2*)(sg + row*128 + f) = __floats2half2_rn(v0, v1);
            }
        }
}

// ---------------- host launcher ----------------
extern "C" void kernel_launch(void* const* d_in, const int* in_sizes, int n_in,
                              void* d_out, int out_size)
{
    const float* x      = (const float*)d_in[0];
    const float* norm_g = (const float*)d_in[1];
    const float* norm_b = (const float*)d_in[2];
    const float* W1     = (const float*)d_in[3];
    const float* b1     = (const float*)d_in[4];
    const float* aff1_W = (const float*)d_in[5];
    const float* aff1_b = (const float*)d_in[6];
    const float* Wl     = (const float*)d_in[7];
    const float* bl     = (const float*)d_in[8];
    const float* sgu_g  = (const float*)d_in[9];
    const float* sgu_b  = (const float*)d_in[10];
    const float* conv_w = (const float*)d_in[11];
    const float* conv_b = (const float*)d_in[12];
    const float* Wqkv   = (const float*)d_in[13];
    const float* bqkv   = (const float*)d_in[14];
    const float* Wo     = (const float*)d_in[15];
    const float* bo     = (const float*)d_in[16];
    const float* W2     = (const float*)d_in[17];
    const float* b2     = (const float*)d_in[18];
    float* out = (float*)d_out;

    __half *xn, *qkvh, *vnT, *sg, *wqkv, *w1, *wo, *w2, *cwt, *uu, *gateres;
    float *coords;
    cudaGetSymbolAddress((void**)&xn,      g_xn);
    cudaGetSymbolAddress((void**)&qkvh,    g_qkvh);
    cudaGetSymbolAddress((void**)&coords,  g_coords);
    cudaGetSymbolAddress((void**)&uu,      g_u);
    cudaGetSymbolAddress((void**)&vnT,     g_vnT);
    cudaGetSymbolAddress((void**)&gateres, g_gateres);
    cudaGetSymbolAddress((void**)&sg,      g_sg);
    cudaGetSymbolAddress((void**)&wqkv,    g_wqkv);
    cudaGetSymbolAddress((void**)&w1,      g_w1);
    cudaGetSymbolAddress((void**)&wo,      g_wo);
    cudaGetSymbolAddress((void**)&w2,      g_w2);
    cudaGetSymbolAddress((void**)&cwt,     g_cwt);

    const int GEMM_SMEM = (2*128*68) * 4;                       // 69632
    const int ATTN_SMEM = (128*68 + 2*64*68 + 128*36) * 4;      // 88064
    const int CONV_SMEM = (128*68 + 130*68) * 4;                // 70176
    static bool attr_done = false;
    if (!attr_done) {
        cudaFuncSetAttribute(gemm_h<0>,   cudaFuncAttributeMaxDynamicSharedMemorySize, GEMM_SMEM);
        cudaFuncSetAttribute(gemm_h<2>,   cudaFuncAttributeMaxDynamicSharedMemorySize, GEMM_SMEM);
        cudaFuncSetAttribute(fc1_kernel,  cudaFuncAttributeMaxDynamicSharedMemorySize, GEMM_SMEM);
        cudaFuncSetAttribute(attn_kernel, cudaFuncAttributeMaxDynamicSharedMemorySize, ATTN_SMEM);
        cudaFuncSetAttribute(conv_tc,     cudaFuncAttributeMaxDynamicSharedMemorySize, CONV_SMEM);
        attr_done = true;
    }

    // 0) weights -> half (transposed / padded)
    prep_kernel<<<1687, 256>>>(Wqkv, W1, Wo, W2, conv_w, wqkv, w1, wo, w2, cwt);
    // 1) LN(x) -> xn half + coords
    ln_kernel<<<(MT + 7) / 8, 256>>>(x, xn, norm_g, norm_b, coords, Wl, bl);
    // 2) qkv = xn @ Wqkv + bqkv -> qkvh half [row][384]
    {
        dim3 g(3, 975);
        gemm_h<0><<<g, 256, GEMM_SMEM>>>(xn, wqkv, qkvh, bqkv, nullptr);
    }
    // 3) FC1 + fused SGU-LN -> u (half), vnT (half, transposed)
    {
        dim3 g(2, 975);
        fc1_kernel<<<g, 256, GEMM_SMEM>>>(xn, w1, uu, vnT, coords,
                                          b1, aff1_W, aff1_b, sgu_g, sgu_b);
    }
    // 4) fused attention + Wo projection -> gateres (half)
    {
        dim3 g(3, BT);
        attn_kernel<<<g, 256, ATTN_SMEM>>>(qkvh, wo, bo, gateres);
    }
    // 5) conv + gate -> sg (half)
    {
        dim3 g(3, BT);
        conv_tc<<<g, 256, CONV_SMEM>>>(cwt, vnT, conv_b, gateres, uu, sg);
    }
    // 6) out = relu(sg @ W2 + b2) + x
    {
        dim3 g(1, 975);
        gemm_h<2><<<g, 256, GEMM_SMEM>>>(sg, w2, out, b2, x);
    }
}

// round 16
// speedup vs baseline: 1.1291x; 1.0225x over previous
#include <cuda_runtime.h>
#include <cuda_fp16.h>
#include <cstdint>

#define BT 384
#define NN 325
#define MT (BT*NN)     // 124800

// ---------------- scratch (device globals; zero-initialized) -----------
__device__ __half g_xn     [(size_t)MT*128];
__device__ __half g_qkvh   [(size_t)MT*384];
__device__ float  g_coords [(size_t)MT*2];
__device__ __half g_u      [(size_t)MT*128];
__device__ __half g_vnT    [(size_t)BT*130*384];  // rows 0 and 129 stay zero
__device__ __half g_gateres[(size_t)MT*128];
__device__ __half g_wqkv   [384*128];
__device__ __half g_w1     [256*128];
__device__ __half g_wo     [128*128];
__device__ __half g_w2     [128*128];
__device__ __half g_cwt    [3*384*384];           // [tap][n pad384][m pad384]

// ---------------- helpers ----------------
__device__ __forceinline__ unsigned sptr(const void* p) {
    return (unsigned)__cvta_generic_to_shared(p);
}
__device__ __forceinline__ void cp16(unsigned dst, const void* src, bool pred) {
    int sz = pred ? 16 : 0;
    asm volatile("cp.async.ca.shared.global [%0], [%1], 16, %2;\n"
                 :: "r"(dst), "l"(src), "r"(sz));
}
#define CP_COMMIT() asm volatile("cp.async.commit_group;\n")
#define CP_WAIT0()  asm volatile("cp.async.wait_group 0;\n")

__device__ __forceinline__ void ldsm4(unsigned* r, unsigned addr) {
    asm volatile("ldmatrix.sync.aligned.m8n8.x4.shared.b16 {%0,%1,%2,%3}, [%4];\n"
                 : "=r"(r[0]), "=r"(r[1]), "=r"(r[2]), "=r"(r[3]) : "r"(addr));
}
__device__ __forceinline__ void ldsm4t(unsigned* r, unsigned addr) {
    asm volatile("ldmatrix.sync.aligned.m8n8.x4.trans.shared.b16 {%0,%1,%2,%3}, [%4];\n"
                 : "=r"(r[0]), "=r"(r[1]), "=r"(r[2]), "=r"(r[3]) : "r"(addr));
}
__device__ __forceinline__ void mma_f16(float* c, const unsigned* a, unsigned b0, unsigned b1) {
    asm volatile("mma.sync.aligned.m16n8k16.row.col.f32.f16.f16.f32 "
                 "{%0,%1,%2,%3}, {%4,%5,%6,%7}, {%8,%9}, {%0,%1,%2,%3};\n"
                 : "+f"(c[0]), "+f"(c[1]), "+f"(c[2]), "+f"(c[3])
                 : "r"(a[0]), "r"(a[1]), "r"(a[2]), "r"(a[3]), "r"(b0), "r"(b1));
}
__device__ __forceinline__ unsigned h2u(__half2 h) {
    unsigned u; memcpy(&u, &h, 4); return u;
}

// ---------------- prep: weights -> half, transposed --------------------
__global__ __launch_bounds__(256)
void prep_kernel(const float* __restrict__ Wqkv, const float* __restrict__ W1,
                 const float* __restrict__ Wo, const float* __restrict__ W2,
                 const float* __restrict__ cw,
                 __half* __restrict__ oq, __half* __restrict__ o1,
                 __half* __restrict__ oo, __half* __restrict__ o2,
                 __half* __restrict__ ocw)
{
    int i = blockIdx.x * 256 + threadIdx.x;
    if (i < 49152) { int n = i >> 7, k = i & 127;
        oq[n*128 + k] = __float2half_rn(Wqkv[(size_t)k*384 + n]); return; }
    i -= 49152;
    if (i < 32768) { int n = i >> 7, k = i & 127;
        o1[n*128 + k] = __float2half_rn(W1[(size_t)k*256 + n]); return; }
    i -= 32768;
    if (i < 16384) { int n = i >> 7, k = i & 127;
        oo[n*128 + k] = __float2half_rn(Wo[(size_t)k*128 + n]); return; }
    i -= 16384;
    if (i < 16384) { int n = i >> 7, k = i & 127;
        o2[n*128 + k] = __float2half_rn(W2[(size_t)k*128 + n]); return; }
    i -= 16384;
    if (i < 316875) {   // 3*325*325
        int t = i / 105625, rem = i % 105625;
        int n = rem / 325, m = rem % 325;
        ocw[(size_t)t*384*384 + n*384 + m] =
            __float2half_rn(cw[((size_t)n*325 + m)*3 + t]);
    }
}

// ---------------- LayerNorm(x) -> xn half + coords fp32 ----------------
__global__ __launch_bounds__(256)
void ln_kernel(const float* __restrict__ in, __half* __restrict__ out,
               const float* __restrict__ gam, const float* __restrict__ bet,
               float* __restrict__ coords,
               const float* __restrict__ Wl, const float* __restrict__ bl)
{
    int row = blockIdx.x * 8 + (threadIdx.x >> 5);
    if (row >= MT) return;
    int lane = threadIdx.x & 31;
    float4 v = *(const float4*)(in + (size_t)row * 128 + lane * 4);
    float s  = v.x + v.y + v.z + v.w;
    float ss = v.x*v.x + v.y*v.y + v.z*v.z + v.w*v.w;
#pragma unroll
    for (int o = 16; o > 0; o >>= 1) {
        s  += __shfl_xor_sync(0xffffffffu, s,  o);
        ss += __shfl_xor_sync(0xffffffffu, ss, o);
    }
    float mean = s * (1.f/128.f);
    float var  = ss * (1.f/128.f) - mean * mean;
    float r = rsqrtf(var + 1e-5f);
    int c = lane * 4;
    float o0 = (v.x - mean) * r * gam[c+0] + bet[c+0];
    float o1 = (v.y - mean) * r * gam[c+1] + bet[c+1];
    float o2 = (v.z - mean) * r * gam[c+2] + bet[c+2];
    float o3 = (v.w - mean) * r * gam[c+3] + bet[c+3];
    __half2* orow = (__half2*)(out + (size_t)row * 128);
    orow[lane*2]     = __floats2half2_rn(o0, o1);
    orow[lane*2 + 1] = __floats2half2_rn(o2, o3);
    float c0 = o0*Wl[(c+0)*2] + o1*Wl[(c+1)*2] + o2*Wl[(c+2)*2] + o3*Wl[(c+3)*2];
    float c1 = o0*Wl[(c+0)*2+1] + o1*Wl[(c+1)*2+1] + o2*Wl[(c+2)*2+1] + o3*Wl[(c+3)*2+1];
#pragma unroll
    for (int o = 16; o > 0; o >>= 1) {
        c0 += __shfl_xor_sync(0xffffffffu, c0, o);
        c1 += __shfl_xor_sync(0xffffffffu, c1, o);
    }
    if (lane == 0) {
        coords[(size_t)row*2 + 0] = c0 + bl[0];
        coords[(size_t)row*2 + 1] = c1 + bl[1];
    }
}

// ======== common pieces (tiles: rows of 128 halves = 64 u32, stride 68) =
#define WARP_DECLS \
    const int lane = tid & 31, wid = tid >> 5; \
    const int wm = wid >> 1, wn = wid & 1;     \
    const int qg = lane >> 2, rg = lane & 3;

#define MAINLOOP_128(As, Bs) do {                                            \
    unsigned aaddr[2], baddr[4];                                             \
    _Pragma("unroll")                                                        \
    for (int mt = 0; mt < 2; mt++)                                           \
        aaddr[mt] = sptr((As) + (wm*32 + mt*16 + (lane & 15))*68 + ((lane >> 4) << 2)); \
    _Pragma("unroll")                                                        \
    for (int p = 0; p < 4; p++)                                              \
        baddr[p] = sptr((Bs) + (wn*64 + p*16 + (lane & 7) + ((lane >> 4) << 3))*68 + (((lane >> 3) & 1) << 2)); \
    _Pragma("unroll")                                                        \
    for (int s = 0; s < 8; s++) {                                            \
        unsigned a[2][4], b[4][4];                                           \
        _Pragma("unroll")                                                    \
        for (int mt = 0; mt < 2; mt++) ldsm4(a[mt], aaddr[mt] + s*32);       \
        _Pragma("unroll")                                                    \
        for (int p = 0; p < 4; p++) ldsm4(b[p], baddr[p] + s*32);            \
        _Pragma("unroll")                                                    \
        for (int mt = 0; mt < 2; mt++)                                       \
            _Pragma("unroll")                                                \
            for (int p = 0; p < 4; p++) {                                    \
                mma_f16(acc[mt][2*p],     a[mt], b[p][0], b[p][1]);          \
                mma_f16(acc[mt][2*p + 1], a[mt], b[p][2], b[p][3]);          \
            }                                                                \
    }                                                                        \
} while (0)

#define LOAD_AB_128(As, Bs, Aptr, Bptr) do {                                 \
    _Pragma("unroll")                                                        \
    for (int i = 0; i < 8; i++) {                                            \
        int lin = tid + 256*i; int r = lin >> 4, ch = lin & 15;              \
        cp16(sptr((As) + r*68 + ch*4), (Aptr) + (size_t)r*128 + ch*8, true); \
    }                                                                        \
    _Pragma("unroll")                                                        \
    for (int i = 0; i < 8; i++) {                                            \
        int lin = tid + 256*i; int r = lin >> 4, ch = lin & 15;              \
        cp16(sptr((Bs) + r*68 + ch*4), (Bptr) + (size_t)r*128 + ch*8, true); \
    }                                                                        \
    CP_COMMIT(); CP_WAIT0(); __syncthreads();                                \
} while (0)

#define ACC_DECL float acc[2][8][4];                                         \
    _Pragma("unroll") for (int a_=0;a_<2;a_++)                               \
    _Pragma("unroll") for (int b_=0;b_<8;b_++)                               \
    _Pragma("unroll") for (int c_=0;c_<4;c_++) acc[a_][b_][c_] = 0.f;

// ---------------- dense GEMM (qkv): EPI +bias -> half [row][384] --------
__global__ __launch_bounds__(256)
void gemm_h(const __half* __restrict__ A, const __half* __restrict__ Bw,
            __half* __restrict__ Cout, const float* __restrict__ bias)
{
    extern __shared__ unsigned sm[];
    unsigned* As = sm;             // [128][68]
    unsigned* Bs = sm + 128*68;    // [128][68]
    const int tid = threadIdx.x;
    const int row0 = blockIdx.y * 128, col0 = blockIdx.x * 128;
    LOAD_AB_128(As, Bs, A + (size_t)row0*128, Bw + (size_t)col0*128);
    WARP_DECLS
    ACC_DECL
    MAINLOOP_128(As, Bs);
#pragma unroll
    for (int mt = 0; mt < 2; mt++)
#pragma unroll
        for (int i2 = 0; i2 < 2; i2++) {
            int r = row0 + wm*32 + mt*16 + qg + i2*8;
#pragma unroll
            for (int nt = 0; nt < 8; nt++) {
                int c = col0 + wn*64 + nt*8 + rg*2;
                float v0 = acc[mt][nt][i2*2]     + bias[c];
                float v1 = acc[mt][nt][i2*2 + 1] + bias[c + 1];
                *(__half2*)(Cout + (size_t)r*384 + c) = __floats2half2_rn(v0, v1);
            }
        }
}

// ---------------- FC1 + fused SGU-LN (u half, vnT half transposed) ------
__global__ __launch_bounds__(256)
void fc1_kernel(const __half* __restrict__ A, const __half* __restrict__ Bw,
                __half* __restrict__ u, __half* __restrict__ vnT,
                const float* __restrict__ coords,
                const float* __restrict__ b1,
                const float* __restrict__ aW, const float* __restrict__ ab,
                const float* __restrict__ sgu_g, const float* __restrict__ sgu_b)
{
    extern __shared__ unsigned sm[];
    unsigned* As = sm;
    unsigned* Bs = sm + 128*68;
    const int tid = threadIdx.x;
    const int row0 = blockIdx.y * 128, col0 = blockIdx.x * 128;
    LOAD_AB_128(As, Bs, A + (size_t)row0*128, Bw + (size_t)col0*128);
    WARP_DECLS
    ACC_DECL
    MAINLOOP_128(As, Bs);
    float sums[2][2] = {{0,0},{0,0}}, sqs[2][2] = {{0,0},{0,0}};
#pragma unroll
    for (int mt = 0; mt < 2; mt++)
#pragma unroll
        for (int i2 = 0; i2 < 2; i2++) {
            int r = row0 + wm*32 + mt*16 + qg + i2*8;
            float c0v = coords[(size_t)r*2], c1v = coords[(size_t)r*2 + 1];
#pragma unroll
            for (int nt = 0; nt < 8; nt++)
#pragma unroll
                for (int j = 0; j < 2; j++) {
                    int c = col0 + wn*64 + nt*8 + rg*2 + j;
                    float v = acc[mt][nt][i2*2 + j] + b1[c] + c0v*aW[c] + c1v*aW[256 + c] + ab[c];
                    v = fmaxf(v, 0.f);
                    acc[mt][nt][i2*2 + j] = v;
                    sums[mt][i2] += v;
                    sqs[mt][i2]  += v * v;
                }
        }
    if (col0 == 0) {
#pragma unroll
        for (int mt = 0; mt < 2; mt++)
#pragma unroll
            for (int i2 = 0; i2 < 2; i2++) {
                int r = row0 + wm*32 + mt*16 + qg + i2*8;
#pragma unroll
                for (int nt = 0; nt < 8; nt++) {
                    int c = wn*64 + nt*8 + rg*2;
                    *(__half2*)(u + (size_t)r*128 + c) =
                        __floats2half2_rn(acc[mt][nt][i2*2], acc[mt][nt][i2*2 + 1]);
                }
            }
    } else {
        float* rowstat = (float*)As;   // reuse smem: [128][4]
        __syncthreads();
#pragma unroll
        for (int mt = 0; mt < 2; mt++)
#pragma unroll
            for (int i2 = 0; i2 < 2; i2++) {
                float s = sums[mt][i2], q = sqs[mt][i2];
                s += __shfl_xor_sync(0xffffffffu, s, 1);
                s += __shfl_xor_sync(0xffffffffu, s, 2);
                q += __shfl_xor_sync(0xffffffffu, q, 1);
                q += __shfl_xor_sync(0xffffffffu, q, 2);
                if (rg == 0) {
                    int rl = wm*32 + mt*16 + qg + i2*8;
                    rowstat[rl*4 + wn*2 + 0] = s;
                    rowstat[rl*4 + wn*2 + 1] = q;
                }
            }
        __syncthreads();
#pragma unroll
        for (int mt = 0; mt < 2; mt++)
#pragma unroll
            for (int i2 = 0; i2 < 2; i2++) {
                int rl = wm*32 + mt*16 + qg + i2*8;
                int r = row0 + rl;
                float s = rowstat[rl*4] + rowstat[rl*4 + 2];
                float q = rowstat[rl*4 + 1] + rowstat[rl*4 + 3];
                float mean = s * (1.f/128.f);
                float var  = q * (1.f/128.f) - mean * mean;
                float rinv = rsqrtf(var + 1e-5f);
                int bt = r / NN, node = r - bt * NN;
#pragma unroll
                for (int nt = 0; nt < 8; nt++)
#pragma unroll
                    for (int j = 0; j < 2; j++) {
                        int f = wn*64 + nt*8 + rg*2 + j;
                        float v = (acc[mt][nt][i2*2 + j] - mean) * rinv * sgu_g[f] + sgu_b[f];
                        vnT[((size_t)bt*130 + f + 1)*384 + node] = __float2half_rn(v);
                    }
            }
    }
}

// ---------------- flash attention + fused Wo: grid (3, BT) --------------
__global__ __launch_bounds__(256)
void attn_kernel(const __half* __restrict__ qkvh, const __half* __restrict__ wo,
                 const float* __restrict__ bo, __half* __restrict__ gateres)
{
    extern __shared__ unsigned sm[];
    unsigned* qs = sm;              // [128][68]
    unsigned* ks = sm + 128*68;     // [64][68]   (contiguous with vs)
    unsigned* vs = ks + 64*68;      // [64][68]
    unsigned* Pb = vs + 64*68;      // [128][36]
    const int bt = blockIdx.y, q0 = blockIdx.x * 128;
    const int tid = threadIdx.x;
    const __half* base = qkvh + (size_t)bt * NN * 384;

#pragma unroll
    for (int i = 0; i < 8; i++) {
        int lin = tid + 256*i; int r = lin >> 4, ch = lin & 15;
        int gr = min(q0 + r, NN - 1); bool p = (q0 + r) < NN;
        cp16(sptr(qs + r*68 + ch*4), base + (size_t)gr*384 + ch*8, p);
    }
#define LKV(c0) do {                                                         \
        _Pragma("unroll")                                                    \
        for (int i = 0; i < 4; i++) {                                        \
            int lin = tid + 256*i; int r = lin >> 4, ch = lin & 15;          \
            int gr = min((c0) + r, NN - 1); bool p = ((c0) + r) < NN;        \
            cp16(sptr(ks + r*68 + ch*4), base + (size_t)gr*384 + 128 + ch*8, p); \
            cp16(sptr(vs + r*68 + ch*4), base + (size_t)gr*384 + 256 + ch*8, p); \
        }                                                                    \
    } while (0)
    LKV(0);
    CP_COMMIT(); CP_WAIT0(); __syncthreads();

    const int lane = tid & 31, wid = tid >> 5;
    const int qg = lane >> 2, rg = lane & 3;
    const int R = wid * 16;
    float Oacc[16][4];
#pragma unroll
    for (int a_=0;a_<16;a_++)
#pragma unroll
        for (int c_=0;c_<4;c_++) Oacc[a_][c_] = 0.f;
    float lacc[2] = {0.f, 0.f};

    const unsigned qaddr  = sptr(qs + (R + (lane & 15))*68 + ((lane >> 4) << 2));
    const unsigned paddrA = sptr(Pb + (R + (lane & 15))*36 + ((lane >> 4) << 2));
    unsigned kaddr[4], vaddr[8];
#pragma unroll
    for (int p = 0; p < 4; p++)
        kaddr[p] = sptr(ks + (p*16 + (lane & 7) + ((lane >> 4) << 3))*68 + (((lane >> 3) & 1) << 2));
#pragma unroll
    for (int p = 0; p < 8; p++)
        vaddr[p] = sptr(vs + ((lane & 7) + ((lane & 8) ? 8 : 0))*68 + p*8 + ((lane >> 4) << 2));

    for (int it = 0; it < 6; it++) {
        const int c0 = it * 64;
        float S[8][4];
#pragma unroll
        for (int a_=0;a_<8;a_++)
#pragma unroll
            for (int c_=0;c_<4;c_++) S[a_][c_] = 0.f;
#pragma unroll
        for (int s = 0; s < 8; s++) {
            unsigned a[4], b[4];
            ldsm4(a, qaddr + s*32);
#pragma unroll
            for (int p = 0; p < 4; p++) {
                ldsm4(b, kaddr[p] + s*32);
                mma_f16(S[2*p],     a, b[0], b[1]);
                mma_f16(S[2*p + 1], a, b[2], b[3]);
            }
        }
        float rs[2] = {0.f, 0.f};
#pragma unroll
        for (int ntl = 0; ntl < 8; ntl++)
#pragma unroll
            for (int i2 = 0; i2 < 2; i2++) {
                int colb = c0 + ntl*8 + rg*2;
                float p0 = (colb     < NN) ? __expf(S[ntl][i2*2])     : 0.f;
                float p1 = (colb + 1 < NN) ? __expf(S[ntl][i2*2 + 1]) : 0.f;
                __half2 hp = __floats2half2_rn(p0, p1);
                rs[i2] += __half2float(__low2half(hp)) + __half2float(__high2half(hp));
                Pb[(R + qg + i2*8)*36 + ntl*4 + rg] = h2u(hp);
            }
#pragma unroll
        for (int i2 = 0; i2 < 2; i2++) {
            rs[i2] += __shfl_xor_sync(0xffffffffu, rs[i2], 1);
            rs[i2] += __shfl_xor_sync(0xffffffffu, rs[i2], 2);
            lacc[i2] += rs[i2];
        }
        __syncwarp();
#pragma unroll
        for (int s = 0; s < 4; s++) {
            unsigned a[4], b[4];
            ldsm4(a, paddrA + s*32);
#pragma unroll
            for (int p = 0; p < 8; p++) {
                ldsm4t(b, vaddr[p] + s*(16*68*4));
                mma_f16(Oacc[2*p],     a, b[0], b[1]);
                mma_f16(Oacc[2*p + 1], a, b[2], b[3]);
            }
        }
        __syncthreads();
        if (it < 5) {
            LKV((it + 1) * 64);
            CP_COMMIT(); CP_WAIT0(); __syncthreads();
        }
    }
#undef LKV

    // ---- stage normalized O (fp16) into qs; load Wo into ks/vs ----
#pragma unroll
    for (int i2 = 0; i2 < 2; i2++) {
        int rl = R + qg + i2*8;
        float inv = 1.f / lacc[i2];
#pragma unroll
        for (int ng = 0; ng < 16; ng++) {
            __half2 h = __floats2half2_rn(Oacc[ng][i2*2] * inv,
                                          Oacc[ng][i2*2 + 1] * inv);
            qs[rl*68 + ng*4 + rg] = h2u(h);
        }
    }
#pragma unroll
    for (int i = 0; i < 8; i++) {
        int lin = tid + 256*i; int r = lin >> 4, ch = lin & 15;
        cp16(sptr(ks + r*68 + ch*4), wo + (size_t)r*128 + ch*8, true);
    }
    CP_COMMIT(); CP_WAIT0(); __syncthreads();

    // ---- gateres = O @ Wo + bo ----
    float acc2[16][4];
#pragma unroll
    for (int a_=0;a_<16;a_++)
#pragma unroll
        for (int c_=0;c_<4;c_++) acc2[a_][c_] = 0.f;
    unsigned waddr[8];
#pragma unroll
    for (int p = 0; p < 8; p++)
        waddr[p] = sptr(ks + (p*16 + (lane & 7) + ((lane >> 4) << 3))*68 + (((lane >> 3) & 1) << 2));
#pragma unroll
    for (int s = 0; s < 8; s++) {
        unsigned a[4], b[4];
        ldsm4(a, qaddr + s*32);
#pragma unroll
        for (int p = 0; p < 8; p++) {
            ldsm4(b, waddr[p] + s*32);
            mma_f16(acc2[2*p],     a, b[0], b[1]);
            mma_f16(acc2[2*p + 1], a, b[2], b[3]);
        }
    }
#pragma unroll
    for (int i2 = 0; i2 < 2; i2++) {
        int n = q0 + R + qg + i2*8;
        if (n >= NN) continue;
        __half* grow = gateres + ((size_t)bt * NN + n) * 128;
#pragma unroll
        for (int nt = 0; nt < 16; nt++) {
            int c = nt*8 + rg*2;
            *(__half2*)(grow + c) =
                __floats2half2_rn(acc2[nt][i2*2]     + bo[c],
                                  acc2[nt][i2*2 + 1] + bo[c + 1]);
        }
    }
}

// ---------------- conv + gate + fused W2 + ReLU + residual --------------
__global__ __launch_bounds__(256, 2)
void conv_tc(const __half* __restrict__ cwt, const __half* __restrict__ vnT,
             const float* __restrict__ cb, const __half* __restrict__ gres,
             const __half* __restrict__ u, const __half* __restrict__ w2,
             const float* __restrict__ b2, const float* __restrict__ x,
             float* __restrict__ out)
{
    extern __shared__ unsigned sm[];
    unsigned* As = sm;             // [128][68]  cwt rows n / sg staging
    unsigned* Bs = sm + 128*68;    // [130][68]  vnT rows f(+1) / W2
    const int bt = blockIdx.y, n0 = blockIdx.x * 128;
    const int tid = threadIdx.x;
    const __half* vb = vnT + (size_t)bt * 130 * 384;
    WARP_DECLS
    ACC_DECL

    unsigned aaddr[2], baddr[4];
#pragma unroll
    for (int mt = 0; mt < 2; mt++)
        aaddr[mt] = sptr(As + (wm*32 + mt*16 + (lane & 15))*68 + ((lane >> 4) << 2));
#pragma unroll
    for (int p = 0; p < 4; p++)
        baddr[p] = sptr(Bs + (wn*64 + p*16 + (lane & 7) + ((lane >> 4) << 3))*68 + (((lane >> 3) & 1) << 2));

    for (int mc = 0; mc < 3; mc++) {
        for (int tap = 0; tap < 3; tap++) {
            if (mc || tap) __syncthreads();
            if (tap == 0) {
#pragma unroll
                for (int i = 0; i < 9; i++) {
                    int lin = tid + 256*i;
                    if (lin < 2080) {
                        int r = lin >> 4, ch = lin & 15;
                        cp16(sptr(Bs + r*68 + ch*4),
                             vb + (size_t)r*384 + mc*128 + ch*8, true);
                    }
                }
            }
#pragma unroll
            for (int i = 0; i < 8; i++) {
                int lin = tid + 256*i; int r = lin >> 4, ch = lin & 15;
                cp16(sptr(As + r*68 + ch*4),
                     cwt + ((size_t)tap*384 + n0 + r)*384 + mc*128 + ch*8, true);
            }
            CP_COMMIT(); CP_WAIT0(); __syncthreads();
            const int toff = tap * 272;
#pragma unroll
            for (int s = 0; s < 8; s++) {
                unsigned a[2][4], b[4][4];
#pragma unroll
                for (int mt = 0; mt < 2; mt++) ldsm4(a[mt], aaddr[mt] + s*32);
#pragma unroll
                for (int p = 0; p < 4; p++) ldsm4(b[p], baddr[p] + toff + s*32);
#pragma unroll
                for (int mt = 0; mt < 2; mt++)
#pragma unroll
                    for (int p = 0; p < 4; p++) {
                        mma_f16(acc[mt][2*p],     a[mt], b[p][0], b[p][1]);
                        mma_f16(acc[mt][2*p + 1], a[mt], b[p][2], b[p][3]);
                    }
            }
        }
    }
    // ---- gate epilogue -> stage sg (fp16) into As; zeros for n >= NN ---
    __syncthreads();
#pragma unroll
    for (int mt = 0; mt < 2; mt++)
#pragma unroll
        for (int i2 = 0; i2 < 2; i2++) {
            int nl = wm*32 + mt*16 + qg + i2*8;
            int n = n0 + nl;
            bool ok = (n < NN);
            size_t row = (size_t)bt * NN + (ok ? n : 0);
            float bias = ok ? cb[n] : 0.f;
#pragma unroll
            for (int nt = 0; nt < 8; nt++) {
                int f = wn*64 + nt*8 + rg*2;
                __half2 hv;
                if (ok) {
                    __half2 gh = *(const __half2*)(gres + row*128 + f);
                    __half2 uh = *(const __half2*)(u + row*128 + f);
                    float v0 = (acc[mt][nt][i2*2]     + bias + __half2float(__low2half(gh)))
                             * __half2float(__low2half(uh));
                    float v1 = (acc[mt][nt][i2*2 + 1] + bias + __half2float(__high2half(gh)))
                             * __half2float(__high2half(uh));
                    hv = __floats2half2_rn(v0, v1);
                } else {
                    hv = __floats2half2_rn(0.f, 0.f);
                }
                As[nl*68 + wn*32 + nt*4 + rg] = h2u(hv);
            }
        }
    // ---- load W2 into Bs, one more 128-K MMA pass: out = relu(sg@W2+b2)+x
#pragma unroll
    for (int i = 0; i < 8; i++) {
        int lin = tid + 256*i; int r = lin >> 4, ch = lin & 15;
        cp16(sptr(Bs + r*68 + ch*4), w2 + (size_t)r*128 + ch*8, true);
    }
    CP_COMMIT(); CP_WAIT0(); __syncthreads();
    {
        ACC_DECL
        MAINLOOP_128(As, Bs);
#pragma unroll
        for (int mt = 0; mt < 2; mt++)
#pragma unroll
            for (int i2 = 0; i2 < 2; i2++) {
                int n = n0 + wm*32 + mt*16 + qg + i2*8;
                if (n >= NN) continue;
                size_t row = (size_t)bt * NN + n;
#pragma unroll
                for (int nt = 0; nt < 8; nt++) {
                    int c = wn*64 + nt*8 + rg*2;
                    float v0 = fmaxf(acc[mt][nt][i2*2]     + b2[c],     0.f) + x[row*128 + c];
                    float v1 = fmaxf(acc[mt][nt][i2*2 + 1] + b2[c + 1], 0.f) + x[row*128 + c + 1];
                    out[row*128 + c]     = v0;
                    out[row*128 + c + 1] = v1;
                }
            }
    }
}

// ---------------- host launcher ----------------
extern "C" void kernel_launch(void* const* d_in, const int* in_sizes, int n_in,
                              void* d_out, int out_size)
{
    const float* x      = (const float*)d_in[0];
    const float* norm_g = (const float*)d_in[1];
    const float* norm_b = (const float*)d_in[2];
    const float* W1     = (const float*)d_in[3];
    const float* b1     = (const float*)d_in[4];
    const float* aff1_W = (const float*)d_in[5];
    const float* aff1_b = (const float*)d_in[6];
    const float* Wl     = (const float*)d_in[7];
    const float* bl     = (const float*)d_in[8];
    const float* sgu_g  = (const float*)d_in[9];
    const float* sgu_b  = (const float*)d_in[10];
    const float* conv_w = (const float*)d_in[11];
    const float* conv_b = (const float*)d_in[12];
    const float* Wqkv   = (const float*)d_in[13];
    const float* bqkv   = (const float*)d_in[14];
    const float* Wo     = (const float*)d_in[15];
    const float* bo     = (const float*)d_in[16];
    const float* W2     = (const float*)d_in[17];
    const float* b2     = (const float*)d_in[18];
    float* out = (float*)d_out;

    __half *xn, *qkvh, *vnT, *wqkv, *w1, *wo, *w2, *cwt, *uu, *gateres;
    float *coords;
    cudaGetSymbolAddress((void**)&xn,      g_xn);
    cudaGetSymbolAddress((void**)&qkvh,    g_qkvh);
    cudaGetSymbolAddress((void**)&coords,  g_coords);
    cudaGetSymbolAddress((void**)&uu,      g_u);
    cudaGetSymbolAddress((void**)&vnT,     g_vnT);
    cudaGetSymbolAddress((void**)&gateres, g_gateres);
    cudaGetSymbolAddress((void**)&wqkv,    g_wqkv);
    cudaGetSymbolAddress((void**)&w1,      g_w1);
    cudaGetSymbolAddress((void**)&wo,      g_wo);
    cudaGetSymbolAddress((void**)&w2,      g_w2);
    cudaGetSymbolAddress((void**)&cwt,     g_cwt);

    const int GEMM_SMEM = (2*128*68) * 4;                       // 69632
    const int ATTN_SMEM = (128*68 + 2*64*68 + 128*36) * 4;      // 88064
    const int CONV_SMEM = (128*68 + 130*68) * 4;                // 70176
    static bool attr_done = false;
    if (!attr_done) {
        cudaFuncSetAttribute(gemm_h,      cudaFuncAttributeMaxDynamicSharedMemorySize, GEMM_SMEM);
        cudaFuncSetAttribute(fc1_kernel,  cudaFuncAttributeMaxDynamicSharedMemorySize, GEMM_SMEM);
        cudaFuncSetAttribute(attn_kernel, cudaFuncAttributeMaxDynamicSharedMemorySize, ATTN_SMEM);
        cudaFuncSetAttribute(conv_tc,     cudaFuncAttributeMaxDynamicSharedMemorySize, CONV_SMEM);
        attr_done = true;
    }

    // 0) weights -> half (transposed / padded)
    prep_kernel<<<1687, 256>>>(Wqkv, W1, Wo, W2, conv_w, wqkv, w1, wo, w2, cwt);
    // 1) LN(x) -> xn half + coords
    ln_kernel<<<(MT + 7) / 8, 256>>>(x, xn, norm_g, norm_b, coords, Wl, bl);
    // 2) qkv = xn @ Wqkv + bqkv -> qkvh half [row][384]
    {
        dim3 g(3, 975);
        gemm_h<<<g, 256, GEMM_SMEM>>>(xn, wqkv, qkvh, bqkv);
    }
    // 3) FC1 + fused SGU-LN -> u (half), vnT (half, transposed)
    {
        dim3 g(2, 975);
        fc1_kernel<<<g, 256, GEMM_SMEM>>>(xn, w1, uu, vnT, coords,
                                          b1, aff1_W, aff1_b, sgu_g, sgu_b);
    }
    // 4) fused attention + Wo projection -> gateres (half)
    {
        dim3 g(3, BT);
        attn_kernel<<<g, 256, ATTN_SMEM>>>(qkvh, wo, bo, gateres);
    }
    // 5) conv + gate + W2 + ReLU + residual -> out (fp32)
    {
        dim3 g(3, BT);
        conv_tc<<<g, 256, CONV_SMEM>>>(cwt, vnT, conv_b, gateres, uu,
                                       w2, b2, x, out);
    }
}

// round 17
// speedup vs baseline: 1.2215x; 1.0818x over previous
#include <cuda_runtime.h>
#include <cuda_fp16.h>
#include <cstdint>

#define BT 384
#define NN 325
#define MT (BT*NN)     // 124800

// ---------------- scratch (device globals; zero-initialized) -----------
__device__ __half g_xn     [(size_t)MT*128];
__device__ __half g_qkvh   [(size_t)MT*384];
__device__ float  g_coords [(size_t)MT*2];
__device__ __half g_u      [(size_t)MT*128];
__device__ __half g_vnT    [(size_t)BT*130*384];  // rows 0 and 129 stay zero
__device__ __half g_gateres[(size_t)MT*128];
__device__ __half g_wqkv   [384*128];
__device__ __half g_w1     [256*128];
__device__ __half g_wo     [128*128];
__device__ __half g_w2     [128*128];
__device__ __half g_cwt    [3*384*384];           // [tap][n pad384][m pad384]

// ---------------- helpers ----------------
__device__ __forceinline__ unsigned sptr(const void* p) {
    return (unsigned)__cvta_generic_to_shared(p);
}
__device__ __forceinline__ void cp16(unsigned dst, const void* src, bool pred) {
    int sz = pred ? 16 : 0;
    asm volatile("cp.async.ca.shared.global [%0], [%1], 16, %2;\n"
                 :: "r"(dst), "l"(src), "r"(sz));
}
#define CP_COMMIT() asm volatile("cp.async.commit_group;\n")
#define CP_WAIT0()  asm volatile("cp.async.wait_group 0;\n")
#define CP_WAIT1()  asm volatile("cp.async.wait_group 1;\n")

__device__ __forceinline__ void ldsm4(unsigned* r, unsigned addr) {
    asm volatile("ldmatrix.sync.aligned.m8n8.x4.shared.b16 {%0,%1,%2,%3}, [%4];\n"
                 : "=r"(r[0]), "=r"(r[1]), "=r"(r[2]), "=r"(r[3]) : "r"(addr));
}
__device__ __forceinline__ void ldsm4t(unsigned* r, unsigned addr) {
    asm volatile("ldmatrix.sync.aligned.m8n8.x4.trans.shared.b16 {%0,%1,%2,%3}, [%4];\n"
                 : "=r"(r[0]), "=r"(r[1]), "=r"(r[2]), "=r"(r[3]) : "r"(addr));
}
__device__ __forceinline__ void mma_f16(float* c, const unsigned* a, unsigned b0, unsigned b1) {
    asm volatile("mma.sync.aligned.m16n8k16.row.col.f32.f16.f16.f32 "
                 "{%0,%1,%2,%3}, {%4,%5,%6,%7}, {%8,%9}, {%0,%1,%2,%3};\n"
                 : "+f"(c[0]), "+f"(c[1]), "+f"(c[2]), "+f"(c[3])
                 : "r"(a[0]), "r"(a[1]), "r"(a[2]), "r"(a[3]), "r"(b0), "r"(b1));
}
__device__ __forceinline__ unsigned h2u(__half2 h) {
    unsigned u; memcpy(&u, &h, 4); return u;
}

// ---------------- prep: weights -> half, transposed --------------------
__global__ __launch_bounds__(256)
void prep_kernel(const float* __restrict__ Wqkv, const float* __restrict__ W1,
                 const float* __restrict__ Wo, const float* __restrict__ W2,
                 const float* __restrict__ cw,
                 __half* __restrict__ oq, __half* __restrict__ o1,
                 __half* __restrict__ oo, __half* __restrict__ o2,
                 __half* __restrict__ ocw)
{
    int i = blockIdx.x * 256 + threadIdx.x;
    if (i < 49152) { int n = i >> 7, k = i & 127;
        oq[n*128 + k] = __float2half_rn(Wqkv[(size_t)k*384 + n]); return; }
    i -= 49152;
    if (i < 32768) { int n = i >> 7, k = i & 127;
        o1[n*128 + k] = __float2half_rn(W1[(size_t)k*256 + n]); return; }
    i -= 32768;
    if (i < 16384) { int n = i >> 7, k = i & 127;
        oo[n*128 + k] = __float2half_rn(Wo[(size_t)k*128 + n]); return; }
    i -= 16384;
    if (i < 16384) { int n = i >> 7, k = i & 127;
        o2[n*128 + k] = __float2half_rn(W2[(size_t)k*128 + n]); return; }
    i -= 16384;
    if (i < 316875) {   // 3*325*325
        int t = i / 105625, rem = i % 105625;
        int n = rem / 325, m = rem % 325;
        ocw[(size_t)t*384*384 + n*384 + m] =
            __float2half_rn(cw[((size_t)n*325 + m)*3 + t]);
    }
}

// ---------------- LayerNorm(x) -> xn half + coords fp32 ----------------
__global__ __launch_bounds__(256)
void ln_kernel(const float* __restrict__ in, __half* __restrict__ out,
               const float* __restrict__ gam, const float* __restrict__ bet,
               float* __restrict__ coords,
               const float* __restrict__ Wl, const float* __restrict__ bl)
{
    int row = blockIdx.x * 8 + (threadIdx.x >> 5);
    if (row >= MT) return;
    int lane = threadIdx.x & 31;
    float4 v = *(const float4*)(in + (size_t)row * 128 + lane * 4);
    float s  = v.x + v.y + v.z + v.w;
    float ss = v.x*v.x + v.y*v.y + v.z*v.z + v.w*v.w;
#pragma unroll
    for (int o = 16; o > 0; o >>= 1) {
        s  += __shfl_xor_sync(0xffffffffu, s,  o);
        ss += __shfl_xor_sync(0xffffffffu, ss, o);
    }
    float mean = s * (1.f/128.f);
    float var  = ss * (1.f/128.f) - mean * mean;
    float r = rsqrtf(var + 1e-5f);
    int c = lane * 4;
    float o0 = (v.x - mean) * r * gam[c+0] + bet[c+0];
    float o1 = (v.y - mean) * r * gam[c+1] + bet[c+1];
    float o2 = (v.z - mean) * r * gam[c+2] + bet[c+2];
    float o3 = (v.w - mean) * r * gam[c+3] + bet[c+3];
    __half2* orow = (__half2*)(out + (size_t)row * 128);
    orow[lane*2]     = __floats2half2_rn(o0, o1);
    orow[lane*2 + 1] = __floats2half2_rn(o2, o3);
    float c0 = o0*Wl[(c+0)*2] + o1*Wl[(c+1)*2] + o2*Wl[(c+2)*2] + o3*Wl[(c+3)*2];
    float c1 = o0*Wl[(c+0)*2+1] + o1*Wl[(c+1)*2+1] + o2*Wl[(c+2)*2+1] + o3*Wl[(c+3)*2+1];
#pragma unroll
    for (int o = 16; o > 0; o >>= 1) {
        c0 += __shfl_xor_sync(0xffffffffu, c0, o);
        c1 += __shfl_xor_sync(0xffffffffu, c1, o);
    }
    if (lane == 0) {
        coords[(size_t)row*2 + 0] = c0 + bl[0];
        coords[(size_t)row*2 + 1] = c1 + bl[1];
    }
}

// ======== common pieces (tiles: rows of 128 halves = 64 u32, stride 68) =
#define WARP_DECLS \
    const int lane = tid & 31, wid = tid >> 5; \
    const int wm = wid >> 1, wn = wid & 1;     \
    const int qg = lane >> 2, rg = lane & 3;

#define MAINLOOP_128(As, Bs) do {                                            \
    unsigned aaddr[2], baddr[4];                                             \
    _Pragma("unroll")                                                        \
    for (int mt = 0; mt < 2; mt++)                                           \
        aaddr[mt] = sptr((As) + (wm*32 + mt*16 + (lane & 15))*68 + ((lane >> 4) << 2)); \
    _Pragma("unroll")                                                        \
    for (int p = 0; p < 4; p++)                                              \
        baddr[p] = sptr((Bs) + (wn*64 + p*16 + (lane & 7) + ((lane >> 4) << 3))*68 + (((lane >> 3) & 1) << 2)); \
    _Pragma("unroll")                                                        \
    for (int s = 0; s < 8; s++) {                                            \
        unsigned a[2][4], b[4][4];                                           \
        _Pragma("unroll")                                                    \
        for (int mt = 0; mt < 2; mt++) ldsm4(a[mt], aaddr[mt] + s*32);       \
        _Pragma("unroll")                                                    \
        for (int p = 0; p < 4; p++) ldsm4(b[p], baddr[p] + s*32);            \
        _Pragma("unroll")                                                    \
        for (int mt = 0; mt < 2; mt++)                                       \
            _Pragma("unroll")                                                \
            for (int p = 0; p < 4; p++) {                                    \
                mma_f16(acc[mt][2*p],     a[mt], b[p][0], b[p][1]);          \
                mma_f16(acc[mt][2*p + 1], a[mt], b[p][2], b[p][3]);          \
            }                                                                \
    }                                                                        \
} while (0)

#define LOAD_AB_128(As, Bs, Aptr, Bptr) do {                                 \
    _Pragma("unroll")                                                        \
    for (int i = 0; i < 8; i++) {                                            \
        int lin = tid + 256*i; int r = lin >> 4, ch = lin & 15;              \
        cp16(sptr((As) + r*68 + ch*4), (Aptr) + (size_t)r*128 + ch*8, true); \
    }                                                                        \
    _Pragma("unroll")                                                        \
    for (int i = 0; i < 8; i++) {                                            \
        int lin = tid + 256*i; int r = lin >> 4, ch = lin & 15;              \
        cp16(sptr((Bs) + r*68 + ch*4), (Bptr) + (size_t)r*128 + ch*8, true); \
    }                                                                        \
    CP_COMMIT(); CP_WAIT0(); __syncthreads();                                \
} while (0)

#define ACC_DECL float acc[2][8][4];                                         \
    _Pragma("unroll") for (int a_=0;a_<2;a_++)                               \
    _Pragma("unroll") for (int b_=0;b_<8;b_++)                               \
    _Pragma("unroll") for (int c_=0;c_<4;c_++) acc[a_][b_][c_] = 0.f;

// ---------------- dense GEMM (qkv): EPI +bias -> half [row][384] --------
__global__ __launch_bounds__(256)
void gemm_h(const __half* __restrict__ A, const __half* __restrict__ Bw,
            __half* __restrict__ Cout, const float* __restrict__ bias)
{
    extern __shared__ unsigned sm[];
    unsigned* As = sm;             // [128][68]
    unsigned* Bs = sm + 128*68;    // [128][68]
    const int tid = threadIdx.x;
    const int row0 = blockIdx.y * 128, col0 = blockIdx.x * 128;
    LOAD_AB_128(As, Bs, A + (size_t)row0*128, Bw + (size_t)col0*128);
    WARP_DECLS
    ACC_DECL
    MAINLOOP_128(As, Bs);
#pragma unroll
    for (int mt = 0; mt < 2; mt++)
#pragma unroll
        for (int i2 = 0; i2 < 2; i2++) {
            int r = row0 + wm*32 + mt*16 + qg + i2*8;
#pragma unroll
            for (int nt = 0; nt < 8; nt++) {
                int c = col0 + wn*64 + nt*8 + rg*2;
                float v0 = acc[mt][nt][i2*2]     + bias[c];
                float v1 = acc[mt][nt][i2*2 + 1] + bias[c + 1];
                *(__half2*)(Cout + (size_t)r*384 + c) = __floats2half2_rn(v0, v1);
            }
        }
}

// ---------------- FC1 + fused SGU-LN (u half, vnT half transposed) ------
__global__ __launch_bounds__(256)
void fc1_kernel(const __half* __restrict__ A, const __half* __restrict__ Bw,
                __half* __restrict__ u, __half* __restrict__ vnT,
                const float* __restrict__ coords,
                const float* __restrict__ b1,
                const float* __restrict__ aW, const float* __restrict__ ab,
                const float* __restrict__ sgu_g, const float* __restrict__ sgu_b)
{
    extern __shared__ unsigned sm[];
    unsigned* As = sm;
    unsigned* Bs = sm + 128*68;
    const int tid = threadIdx.x;
    const int row0 = blockIdx.y * 128, col0 = blockIdx.x * 128;
    LOAD_AB_128(As, Bs, A + (size_t)row0*128, Bw + (size_t)col0*128);
    WARP_DECLS
    ACC_DECL
    MAINLOOP_128(As, Bs);
    float sums[2][2] = {{0,0},{0,0}}, sqs[2][2] = {{0,0},{0,0}};
#pragma unroll
    for (int mt = 0; mt < 2; mt++)
#pragma unroll
        for (int i2 = 0; i2 < 2; i2++) {
            int r = row0 + wm*32 + mt*16 + qg + i2*8;
            float c0v = coords[(size_t)r*2], c1v = coords[(size_t)r*2 + 1];
#pragma unroll
            for (int nt = 0; nt < 8; nt++)
#pragma unroll
                for (int j = 0; j < 2; j++) {
                    int c = col0 + wn*64 + nt*8 + rg*2 + j;
                    float v = acc[mt][nt][i2*2 + j] + b1[c] + c0v*aW[c] + c1v*aW[256 + c] + ab[c];
                    v = fmaxf(v, 0.f);
                    acc[mt][nt][i2*2 + j] = v;
                    sums[mt][i2] += v;
                    sqs[mt][i2]  += v * v;
                }
        }
    if (col0 == 0) {
#pragma unroll
        for (int mt = 0; mt < 2; mt++)
#pragma unroll
            for (int i2 = 0; i2 < 2; i2++) {
                int r = row0 + wm*32 + mt*16 + qg + i2*8;
#pragma unroll
                for (int nt = 0; nt < 8; nt++) {
                    int c = wn*64 + nt*8 + rg*2;
                    *(__half2*)(u + (size_t)r*128 + c) =
                        __floats2half2_rn(acc[mt][nt][i2*2], acc[mt][nt][i2*2 + 1]);
                }
            }
    } else {
        float* rowstat = (float*)As;   // reuse smem: [128][4]
        __syncthreads();
#pragma unroll
        for (int mt = 0; mt < 2; mt++)
#pragma unroll
            for (int i2 = 0; i2 < 2; i2++) {
                float s = sums[mt][i2], q = sqs[mt][i2];
                s += __shfl_xor_sync(0xffffffffu, s, 1);
                s += __shfl_xor_sync(0xffffffffu, s, 2);
                q += __shfl_xor_sync(0xffffffffu, q, 1);
                q += __shfl_xor_sync(0xffffffffu, q, 2);
                if (rg == 0) {
                    int rl = wm*32 + mt*16 + qg + i2*8;
                    rowstat[rl*4 + wn*2 + 0] = s;
                    rowstat[rl*4 + wn*2 + 1] = q;
                }
            }
        __syncthreads();
#pragma unroll
        for (int mt = 0; mt < 2; mt++)
#pragma unroll
            for (int i2 = 0; i2 < 2; i2++) {
                int rl = wm*32 + mt*16 + qg + i2*8;
                int r = row0 + rl;
                float s = rowstat[rl*4] + rowstat[rl*4 + 2];
                float q = rowstat[rl*4 + 1] + rowstat[rl*4 + 3];
                float mean = s * (1.f/128.f);
                float var  = q * (1.f/128.f) - mean * mean;
                float rinv = rsqrtf(var + 1e-5f);
                int bt = r / NN, node = r - bt * NN;
#pragma unroll
                for (int nt = 0; nt < 8; nt++)
#pragma unroll
                    for (int j = 0; j < 2; j++) {
                        int f = wn*64 + nt*8 + rg*2 + j;
                        float v = (acc[mt][nt][i2*2 + j] - mean) * rinv * sgu_g[f] + sgu_b[f];
                        vnT[((size_t)bt*130 + f + 1)*384 + node] = __float2half_rn(v);
                    }
            }
    }
}

// ---------------- flash attention + fused Wo: grid (3, BT) --------------
// Pipelined: K loads overlap exp+PV; V loads overlap next S phase.
__global__ __launch_bounds__(256)
void attn_kernel(const __half* __restrict__ qkvh, const __half* __restrict__ wo,
                 const float* __restrict__ bo, __half* __restrict__ gateres)
{
    extern __shared__ unsigned sm[];
    unsigned* qs = sm;              // [128][68]
    unsigned* ks = sm + 128*68;     // [64][68]   (contiguous with vs)
    unsigned* vs = ks + 64*68;      // [64][68]
    unsigned* Pb = vs + 64*68;      // [128][36]
    const int bt = blockIdx.y, q0 = blockIdx.x * 128;
    const int tid = threadIdx.x;
    const __half* base = qkvh + (size_t)bt * NN * 384;

#define LK(c0) do {                                                          \
        _Pragma("unroll")                                                    \
        for (int i = 0; i < 4; i++) {                                        \
            int lin = tid + 256*i; int r = lin >> 4, ch = lin & 15;          \
            int gr = min((c0) + r, NN - 1); bool p = ((c0) + r) < NN;        \
            cp16(sptr(ks + r*68 + ch*4), base + (size_t)gr*384 + 128 + ch*8, p); \
        }                                                                    \
    } while (0)
#define LV(c0) do {                                                          \
        _Pragma("unroll")                                                    \
        for (int i = 0; i < 4; i++) {                                        \
            int lin = tid + 256*i; int r = lin >> 4, ch = lin & 15;          \
            int gr = min((c0) + r, NN - 1); bool p = ((c0) + r) < NN;        \
            cp16(sptr(vs + r*68 + ch*4), base + (size_t)gr*384 + 256 + ch*8, p); \
        }                                                                    \
    } while (0)

    // group A: q + K0 ; group B: V0
#pragma unroll
    for (int i = 0; i < 8; i++) {
        int lin = tid + 256*i; int r = lin >> 4, ch = lin & 15;
        int gr = min(q0 + r, NN - 1); bool p = (q0 + r) < NN;
        cp16(sptr(qs + r*68 + ch*4), base + (size_t)gr*384 + ch*8, p);
    }
    LK(0); CP_COMMIT();
    LV(0); CP_COMMIT();

    const int lane = tid & 31, wid = tid >> 5;
    const int qg = lane >> 2, rg = lane & 3;
    const int R = wid * 16;
    float Oacc[16][4];
#pragma unroll
    for (int a_=0;a_<16;a_++)
#pragma unroll
        for (int c_=0;c_<4;c_++) Oacc[a_][c_] = 0.f;
    float lacc[2] = {0.f, 0.f};

    const unsigned qaddr  = sptr(qs + (R + (lane & 15))*68 + ((lane >> 4) << 2));
    const unsigned paddrA = sptr(Pb + (R + (lane & 15))*36 + ((lane >> 4) << 2));
    unsigned kaddr[4], vaddr[8];
#pragma unroll
    for (int p = 0; p < 4; p++)
        kaddr[p] = sptr(ks + (p*16 + (lane & 7) + ((lane >> 4) << 3))*68 + (((lane >> 3) & 1) << 2));
#pragma unroll
    for (int p = 0; p < 8; p++)
        vaddr[p] = sptr(vs + ((lane & 7) + ((lane & 8) ? 8 : 0))*68 + p*8 + ((lane >> 4) << 2));

    for (int it = 0; it < 6; it++) {
        const int c0 = it * 64;
        CP_WAIT1();             // K_it (and q at it=0) ready; V_it may be in flight
        __syncthreads();
        float S[8][4];
#pragma unroll
        for (int a_=0;a_<8;a_++)
#pragma unroll
            for (int c_=0;c_<4;c_++) S[a_][c_] = 0.f;
#pragma unroll
        for (int s = 0; s < 8; s++) {
            unsigned a[4], b[4];
            ldsm4(a, qaddr + s*32);
#pragma unroll
            for (int p = 0; p < 4; p++) {
                ldsm4(b, kaddr[p] + s*32);
                mma_f16(S[2*p],     a, b[0], b[1]);
                mma_f16(S[2*p + 1], a, b[2], b[3]);
            }
        }
        __syncthreads();        // all warps done reading ks
        if (it < 5) { LK((it + 1) * 64); CP_COMMIT(); }
        float rs[2] = {0.f, 0.f};
#pragma unroll
        for (int ntl = 0; ntl < 8; ntl++)
#pragma unroll
            for (int i2 = 0; i2 < 2; i2++) {
                int colb = c0 + ntl*8 + rg*2;
                float p0 = (colb     < NN) ? __expf(S[ntl][i2*2])     : 0.f;
                float p1 = (colb + 1 < NN) ? __expf(S[ntl][i2*2 + 1]) : 0.f;
                __half2 hp = __floats2half2_rn(p0, p1);
                rs[i2] += __half2float(__low2half(hp)) + __half2float(__high2half(hp));
                Pb[(R + qg + i2*8)*36 + ntl*4 + rg] = h2u(hp);
            }
#pragma unroll
        for (int i2 = 0; i2 < 2; i2++) {
            rs[i2] += __shfl_xor_sync(0xffffffffu, rs[i2], 1);
            rs[i2] += __shfl_xor_sync(0xffffffffu, rs[i2], 2);
            lacc[i2] += rs[i2];
        }
        __syncwarp();
        if (it < 5) CP_WAIT1(); else CP_WAIT0();   // V_it ready
#pragma unroll
        for (int s = 0; s < 4; s++) {
            unsigned a[4], b[4];
            ldsm4(a, paddrA + s*32);
#pragma unroll
            for (int p = 0; p < 8; p++) {
                ldsm4t(b, vaddr[p] + s*(16*68*4));
                mma_f16(Oacc[2*p],     a, b[0], b[1]);
                mma_f16(Oacc[2*p + 1], a, b[2], b[3]);
            }
        }
        __syncthreads();        // all warps done reading vs
        if (it < 5) { LV((it + 1) * 64); CP_COMMIT(); }
    }
#undef LK
#undef LV

    // ---- stage normalized O (fp16) into qs; load Wo into ks/vs ----
#pragma unroll
    for (int i2 = 0; i2 < 2; i2++) {
        int rl = R + qg + i2*8;
        float inv = 1.f / lacc[i2];
#pragma unroll
        for (int ng = 0; ng < 16; ng++) {
            __half2 h = __floats2half2_rn(Oacc[ng][i2*2] * inv,
                                          Oacc[ng][i2*2 + 1] * inv);
            qs[rl*68 + ng*4 + rg] = h2u(h);
        }
    }
#pragma unroll
    for (int i = 0; i < 8; i++) {
        int lin = tid + 256*i; int r = lin >> 4, ch = lin & 15;
        cp16(sptr(ks + r*68 + ch*4), wo + (size_t)r*128 + ch*8, true);
    }
    CP_COMMIT(); CP_WAIT0(); __syncthreads();

    // ---- gateres = O @ Wo + bo ----
    float acc2[16][4];
#pragma unroll
    for (int a_=0;a_<16;a_++)
#pragma unroll
        for (int c_=0;c_<4;c_++) acc2[a_][c_] = 0.f;
    unsigned waddr[8];
#pragma unroll
    for (int p = 0; p < 8; p++)
        waddr[p] = sptr(ks + (p*16 + (lane & 7) + ((lane >> 4) << 3))*68 + (((lane >> 3) & 1) << 2));
#pragma unroll
    for (int s = 0; s < 8; s++) {
        unsigned a[4], b[4];
        ldsm4(a, qaddr + s*32);
#pragma unroll
        for (int p = 0; p < 8; p++) {
            ldsm4(b, waddr[p] + s*32);
            mma_f16(acc2[2*p],     a, b[0], b[1]);
            mma_f16(acc2[2*p + 1], a, b[2], b[3]);
        }
    }
#pragma unroll
    for (int i2 = 0; i2 < 2; i2++) {
        int n = q0 + R + qg + i2*8;
        if (n >= NN) continue;
        __half* grow = gateres + ((size_t)bt * NN + n) * 128;
#pragma unroll
        for (int nt = 0; nt < 16; nt++) {
            int c = nt*8 + rg*2;
            *(__half2*)(grow + c) =
                __floats2half2_rn(acc2[nt][i2*2]     + bo[c],
                                  acc2[nt][i2*2 + 1] + bo[c + 1]);
        }
    }
}

// ---------------- conv + gate + fused W2 + ReLU + residual --------------
// A (cwt) double-buffered with 1-step lookahead; B single-buffered.
__global__ __launch_bounds__(256, 2)
void conv_tc(const __half* __restrict__ cwt, const __half* __restrict__ vnT,
             const float* __restrict__ cb, const __half* __restrict__ gres,
             const __half* __restrict__ u, const __half* __restrict__ w2,
             const float* __restrict__ b2, const float* __restrict__ x,
             float* __restrict__ out)
{
    extern __shared__ unsigned sm[];
    unsigned* As = sm;             // [2][128][68]  cwt tiles / sg staging
    unsigned* Bs = sm + 2*128*68;  // [130][68]     vnT rows / W2
    const int bt = blockIdx.y, n0 = blockIdx.x * 128;
    const int tid = threadIdx.x;
    const __half* vb = vnT + (size_t)bt * 130 * 384;
    WARP_DECLS
    ACC_DECL

#define LAq(q_) do {                                                         \
        int tap_ = (q_) % 3, mc_ = (q_) / 3;                                 \
        unsigned* Ad = As + ((q_) & 1)*128*68;                               \
        _Pragma("unroll")                                                    \
        for (int i = 0; i < 8; i++) {                                        \
            int lin = tid + 256*i; int r = lin >> 4, ch = lin & 15;          \
            cp16(sptr(Ad + r*68 + ch*4),                                     \
                 cwt + ((size_t)tap_*384 + n0 + r)*384 + mc_*128 + ch*8, true); \
        }                                                                    \
    } while (0)
#define LB(mc_) do {                                                         \
        _Pragma("unroll")                                                    \
        for (int i = 0; i < 9; i++) {                                        \
            int lin = tid + 256*i;                                           \
            if (lin < 2080) {                                                \
                int r = lin >> 4, ch = lin & 15;                             \
                cp16(sptr(Bs + r*68 + ch*4),                                 \
                     vb + (size_t)r*384 + (mc_)*128 + ch*8, true);           \
            }                                                                \
        }                                                                    \
    } while (0)

    LB(0); LAq(0); CP_COMMIT();
    LAq(1); CP_COMMIT();

    unsigned baddr[4];
#pragma unroll
    for (int p = 0; p < 4; p++)
        baddr[p] = sptr(Bs + (wn*64 + p*16 + (lane & 7) + ((lane >> 4) << 3))*68 + (((lane >> 3) & 1) << 2));

    for (int q = 0; q < 9; q++) {
        if (q == 3 || q == 6 || q == 8) CP_WAIT0(); else CP_WAIT1();
        __syncthreads();
        const int tap = q % 3;
        unsigned* Ac = As + (q & 1)*128*68;
        unsigned aaddr[2];
#pragma unroll
        for (int mt = 0; mt < 2; mt++)
            aaddr[mt] = sptr(Ac + (wm*32 + mt*16 + (lane & 15))*68 + ((lane >> 4) << 2));
        const int toff = tap * 272;
#pragma unroll
        for (int s = 0; s < 8; s++) {
            unsigned a[2][4], b[4][4];
#pragma unroll
            for (int mt = 0; mt < 2; mt++) ldsm4(a[mt], aaddr[mt] + s*32);
#pragma unroll
            for (int p = 0; p < 4; p++) ldsm4(b[p], baddr[p] + toff + s*32);
#pragma unroll
            for (int mt = 0; mt < 2; mt++)
#pragma unroll
                for (int p = 0; p < 4; p++) {
                    mma_f16(acc[mt][2*p],     a[mt], b[p][0], b[p][1]);
                    mma_f16(acc[mt][2*p + 1], a[mt], b[p][2], b[p][3]);
                }
        }
        __syncthreads();
        bool committed = false;
        if (q + 2 <= 8) { LAq(q + 2); committed = true; }
        if ((q + 1) % 3 == 0 && q + 1 <= 8) { LB((q + 1) / 3); committed = true; }
        if (committed) CP_COMMIT();
    }
#undef LAq
#undef LB
    // ---- gate epilogue -> stage sg (fp16) into As[0]; zeros for n >= NN
    __syncthreads();
#pragma unroll
    for (int mt = 0; mt < 2; mt++)
#pragma unroll
        for (int i2 = 0; i2 < 2; i2++) {
            int nl = wm*32 + mt*16 + qg + i2*8;
            int n = n0 + nl;
            bool ok = (n < NN);
            size_t row = (size_t)bt * NN + (ok ? n : 0);
            float bias = ok ? cb[n] : 0.f;
#pragma unroll
            for (int nt = 0; nt < 8; nt++) {
                int f = wn*64 + nt*8 + rg*2;
                __half2 hv;
                if (ok) {
                    __half2 gh = *(const __half2*)(gres + row*128 + f);
                    __half2 uh = *(const __half2*)(u + row*128 + f);
                    float v0 = (acc[mt][nt][i2*2]     + bias + __half2float(__low2half(gh)))
                             * __half2float(__low2half(uh));
                    float v1 = (acc[mt][nt][i2*2 + 1] + bias + __half2float(__high2half(gh)))
                             * __half2float(__high2half(uh));
                    hv = __floats2half2_rn(v0, v1);
                } else {
                    hv = __floats2half2_rn(0.f, 0.f);
                }
                As[nl*68 + wn*32 + nt*4 + rg] = h2u(hv);
            }
        }
    // ---- load W2 into Bs, one more 128-K MMA pass: out = relu(sg@W2+b2)+x
#pragma unroll
    for (int i = 0; i < 8; i++) {
        int lin = tid + 256*i; int r = lin >> 4, ch = lin & 15;
        cp16(sptr(Bs + r*68 + ch*4), w2 + (size_t)r*128 + ch*8, true);
    }
    CP_COMMIT(); CP_WAIT0(); __syncthreads();
    {
        ACC_DECL
        MAINLOOP_128(As, Bs);
#pragma unroll
        for (int mt = 0; mt < 2; mt++)
#pragma unroll
            for (int i2 = 0; i2 < 2; i2++) {
                int n = n0 + wm*32 + mt*16 + qg + i2*8;
                if (n >= NN) continue;
                size_t row = (size_t)bt * NN + n;
#pragma unroll
                for (int nt = 0; nt < 8; nt++) {
                    int c = wn*64 + nt*8 + rg*2;
                    float v0 = fmaxf(acc[mt][nt][i2*2]     + b2[c],     0.f) + x[row*128 + c];
                    float v1 = fmaxf(acc[mt][nt][i2*2 + 1] + b2[c + 1], 0.f) + x[row*128 + c + 1];
                    out[row*128 + c]     = v0;
                    out[row*128 + c + 1] = v1;
                }
            }
    }
}

// ---------------- host launcher ----------------
extern "C" void kernel_launch(void* const* d_in, const int* in_sizes, int n_in,
                              void* d_out, int out_size)
{
    const float* x      = (const float*)d_in[0];
    const float* norm_g = (const float*)d_in[1];
    const float* norm_b = (const float*)d_in[2];
    const float* W1     = (const float*)d_in[3];
    const float* b1     = (const float*)d_in[4];
    const float* aff1_W = (const float*)d_in[5];
    const float* aff1_b = (const float*)d_in[6];
    const float* Wl     = (const float*)d_in[7];
    const float* bl     = (const float*)d_in[8];
    const float* sgu_g  = (const float*)d_in[9];
    const float* sgu_b  = (const float*)d_in[10];
    const float* conv_w = (const float*)d_in[11];
    const float* conv_b = (const float*)d_in[12];
    const float* Wqkv   = (const float*)d_in[13];
    const float* bqkv   = (const float*)d_in[14];
    const float* Wo     = (const float*)d_in[15];
    const float* bo     = (const float*)d_in[16];
    const float* W2     = (const float*)d_in[17];
    const float* b2     = (const float*)d_in[18];
    float* out = (float*)d_out;

    __half *xn, *qkvh, *vnT, *wqkv, *w1, *wo, *w2, *cwt, *uu, *gateres;
    float *coords;
    cudaGetSymbolAddress((void**)&xn,      g_xn);
    cudaGetSymbolAddress((void**)&qkvh,    g_qkvh);
    cudaGetSymbolAddress((void**)&coords,  g_coords);
    cudaGetSymbolAddress((void**)&uu,      g_u);
    cudaGetSymbolAddress((void**)&vnT,     g_vnT);
    cudaGetSymbolAddress((void**)&gateres, g_gateres);
    cudaGetSymbolAddress((void**)&wqkv,    g_wqkv);
    cudaGetSymbolAddress((void**)&w1,      g_w1);
    cudaGetSymbolAddress((void**)&wo,      g_wo);
    cudaGetSymbolAddress((void**)&w2,      g_w2);
    cudaGetSymbolAddress((void**)&cwt,     g_cwt);

    const int GEMM_SMEM = (2*128*68) * 4;                       // 69632
    const int ATTN_SMEM = (128*68 + 2*64*68 + 128*36) * 4;      // 88064
    const int CONV_SMEM = (2*128*68 + 130*68) * 4;              // 104992
    static bool attr_done = false;
    if (!attr_done) {
        cudaFuncSetAttribute(gemm_h,      cudaFuncAttributeMaxDynamicSharedMemorySize, GEMM_SMEM);
        cudaFuncSetAttribute(fc1_kernel,  cudaFuncAttributeMaxDynamicSharedMemorySize, GEMM_SMEM);
        cudaFuncSetAttribute(attn_kernel, cudaFuncAttributeMaxDynamicSharedMemorySize, ATTN_SMEM);
        cudaFuncSetAttribute(conv_tc,     cudaFuncAttributeMaxDynamicSharedMemorySize, CONV_SMEM);
        attr_done = true;
    }

    // 0) weights -> half (transposed / padded)
    prep_kernel<<<1687, 256>>>(Wqkv, W1, Wo, W2, conv_w, wqkv, w1, wo, w2, cwt);
    // 1) LN(x) -> xn half + coords
    ln_kernel<<<(MT + 7) / 8, 256>>>(x, xn, norm_g, norm_b, coords, Wl, bl);
    // 2) qkv = xn @ Wqkv + bqkv -> qkvh half [row][384]
    {
        dim3 g(3, 975);
        gemm_h<<<g, 256, GEMM_SMEM>>>(xn, wqkv, qkvh, bqkv);
    }
    // 3) FC1 + fused SGU-LN -> u (half), vnT (half, transposed)
    {
        dim3 g(2, 975);
        fc1_kernel<<<g, 256, GEMM_SMEM>>>(xn, w1, uu, vnT, coords,
                                          b1, aff1_W, aff1_b, sgu_g, sgu_b);
    }
    // 4) fused attention + Wo projection -> gateres (half)
    {
        dim3 g(3, BT);
        attn_kernel<<<g, 256, ATTN_SMEM>>>(qkvh, wo, bo, gateres);
    }
    // 5) conv + gate + W2 + ReLU + residual -> out (fp32)
    {
        dim3 g(3, BT);
        conv_tc<<<g, 256, CONV_SMEM>>>(cwt, vnT, conv_b, gateres, uu,
                                       w2, b2, x, out);
    }
}